// round 13
// baseline (speedup 1.0000x reference)
#include <cuda_runtime.h>
#include <cstdint>

#define NUSERS 100000
#define NITEMS 20000
#define NNODES 120000
#define DMOV   192
#define HID    256
#define NGEN   20
#define NTAGS  1128
#define MOVLD  1148
#define ETOT   400000
#define NBLK   ((NNODES + 255) / 256)
#define NCHUNK 4
#define CHUNK  (NNODES / NCHUNK)   // 30000

// ---------------- scratch (static device globals; no allocation) ----------------
__device__ __align__(16) float g_xmov[NITEMS * DMOV];    // item_emb | g | t
__device__ __align__(16) float g_gh  [NITEMS * 64];
__device__ __align__(16) float g_th  [NITEMS * 64];
__device__ __align__(16) float g_hs1 [NNODES * HID];
__device__ __align__(16) float g_out1[NNODES * HID];
__device__ __align__(16) float g_hs2 [NNODES * HID];
__device__ __align__(16) float g_al1 [NNODES * 16];      // [al_s(8) | al_d(8)]
__device__ __align__(16) float g_al2 [NNODES * 2];
__device__ __align__(16) float g_fold1[DMOV * 16];
__device__ __align__(16) float g_fold2[HID * 2];
__device__ __align__(16) float g_bt1 [HID * DMOV];       // Ws1^T tf32
__device__ __align__(16) float g_bt2 [HID * HID];        // Ws2^T tf32
__device__ __align__(16) float g_btt [64 * NTAGS];       // tW1^T tf32
// CSR
__device__ int g_cnt[NNODES];
__device__ int g_cur[NNODES];
__device__ int g_ptr[NNODES + 1];
__device__ int g_bsum[512];
__device__ int g_adj[ETOT];

// ---------------- helpers ----------------
__device__ __forceinline__ uint32_t f2tf32(float f) {
    uint32_t u;
    asm("cvt.rna.tf32.f32 %0, %1;" : "=r"(u) : "f"(f));
    return u;
}
__device__ __forceinline__ float tf32r(float f) { return __uint_as_float(f2tf32(f)); }
__device__ __forceinline__ uint32_t smaddr(const void* p) {
    uint32_t a;
    asm("{ .reg .u64 t; cvta.to.shared.u64 t, %1; cvt.u32.u64 %0, t; }" : "=r"(a) : "l"(p));
    return a;
}
#define CP_ASYNC16(dst, src, sz) \
    asm volatile("cp.async.cg.shared.global [%0], [%1], 16, %2;" \
                 :: "r"(dst), "l"(src), "r"(sz) : "memory")
#define CP_COMMIT() asm volatile("cp.async.commit_group;" ::: "memory")
#define CP_WAIT(n)  asm volatile("cp.async.wait_group %0;" :: "n"(n) : "memory")

// ---------------- tf32 mma.sync GEMM with cp.async staging (2-stage, 3 CTA/SM) ----------------
template <int BN, int WM, int WN, int ACT>
__global__ void __launch_bounds__(256)
mma_gemm_k(const float* __restrict__ A, int lda,
           const float* __restrict__ Bt, int ldb,
           float* __restrict__ C, int ldc,
           int M, int K, const float* __restrict__ bias) {
    constexpr int BM = 128, BK = 32;
    constexpr int SK = BK + 4;
    constexpr int MT = WM / 16, NT = WN / 8;
    constexpr int NWN = BN / WN;
    constexpr int NA = BM * BK / (4 * 256);
    constexpr int NB = BN * BK / (4 * 256);

    extern __shared__ float sm[];
    float* sAb[2]; float* sBb[2];
    sAb[0] = sm;
    sBb[0] = sm + BM * SK;
    sAb[1] = sm + (BM + BN) * SK;
    sBb[1] = sAb[1] + BM * SK;
    const uint32_t sA0 = smaddr(sAb[0]), sB0 = smaddr(sBb[0]);
    const uint32_t sA1 = smaddr(sAb[1]), sB1 = smaddr(sBb[1]);

    const int tid = threadIdx.x, wid = tid >> 5, lane = tid & 31;
    const int wm = wid / NWN, wn = wid % NWN;
    const int group = lane >> 2, qid = lane & 3;
    const int row0 = blockIdx.y * BM, col0 = blockIdx.x * BN;

    float acc[MT][NT][4];
    #pragma unroll
    for (int i = 0; i < MT; i++)
        #pragma unroll
        for (int j = 0; j < NT; j++)
            #pragma unroll
            for (int t = 0; t < 4; t++) acc[i][j][t] = 0.0f;

    const int nt = (K + BK - 1) / BK;

    auto issue = [&](int t) {
        const int k0 = t * BK;
        const uint32_t dA = (t & 1) ? sA1 : sA0;
        const uint32_t dB = (t & 1) ? sB1 : sB0;
        #pragma unroll
        for (int i = 0; i < NA; i++) {
            int idx = tid + i * 256;
            int row = idx >> 3, kv = (idx & 7) * 4;
            int gm = row0 + row, gk = k0 + kv;
            uint32_t sz = (gm < M && gk < K) ? 16u : 0u;
            CP_ASYNC16(dA + (uint32_t)(row * SK + kv) * 4,
                       A + (size_t)gm * lda + gk, sz);
        }
        #pragma unroll
        for (int i = 0; i < NB; i++) {
            int idx = tid + i * 256;
            int row = idx >> 3, kv = (idx & 7) * 4;
            int gk = k0 + kv;
            uint32_t sz = (gk < K) ? 16u : 0u;
            CP_ASYNC16(dB + (uint32_t)(row * SK + kv) * 4,
                       Bt + (size_t)(col0 + row) * ldb + gk, sz);
        }
    };

    issue(0); CP_COMMIT();

    for (int t = 0; t < nt; t++) {
        if (t + 1 < nt) { issue(t + 1); CP_COMMIT(); CP_WAIT(1); }
        else            { CP_WAIT(0); }
        __syncthreads();
        const float* sA = (t & 1) ? sAb[1] : sAb[0];
        const float* sB = (t & 1) ? sBb[1] : sBb[0];
        #pragma unroll
        for (int ks = 0; ks < 4; ks++) {
            const int koff = ks * 8;
            uint32_t af[MT][4], bf[NT][2];
            #pragma unroll
            for (int i = 0; i < MT; i++) {
                const float* p = sA + (wm * WM + i * 16) * SK + koff;
                af[i][0] = __float_as_uint(p[group * SK + qid]);
                af[i][1] = __float_as_uint(p[(group + 8) * SK + qid]);
                af[i][2] = __float_as_uint(p[group * SK + qid + 4]);
                af[i][3] = __float_as_uint(p[(group + 8) * SK + qid + 4]);
            }
            #pragma unroll
            for (int j = 0; j < NT; j++) {
                const float* p = sB + (wn * WN + j * 8 + group) * SK + koff;
                bf[j][0] = __float_as_uint(p[qid]);
                bf[j][1] = __float_as_uint(p[qid + 4]);
            }
            #pragma unroll
            for (int i = 0; i < MT; i++)
                #pragma unroll
                for (int j = 0; j < NT; j++)
                    asm volatile(
                        "mma.sync.aligned.m16n8k8.row.col.f32.tf32.tf32.f32 "
                        "{%0,%1,%2,%3}, {%4,%5,%6,%7}, {%8,%9}, {%0,%1,%2,%3};"
                        : "+f"(acc[i][j][0]), "+f"(acc[i][j][1]),
                          "+f"(acc[i][j][2]), "+f"(acc[i][j][3])
                        : "r"(af[i][0]), "r"(af[i][1]), "r"(af[i][2]), "r"(af[i][3]),
                          "r"(bf[j][0]), "r"(bf[j][1]));
        }
        __syncthreads();
    }

    #pragma unroll
    for (int i = 0; i < MT; i++) {
        #pragma unroll
        for (int j = 0; j < NT; j++) {
            int r0 = row0 + wm * WM + i * 16 + group;
            int c0 = col0 + wn * WN + j * 8 + qid * 2;
            float b0 = bias ? bias[c0] : 0.f, b1 = bias ? bias[c0 + 1] : 0.f;
            float v0 = acc[i][j][0] + b0, v1 = acc[i][j][1] + b1;
            float v2 = acc[i][j][2] + b0, v3 = acc[i][j][3] + b1;
            if (ACT == 1) {
                v0 = fmaxf(v0, 0.f); v1 = fmaxf(v1, 0.f);
                v2 = fmaxf(v2, 0.f); v3 = fmaxf(v3, 0.f);
            }
            if (r0 < M)     *reinterpret_cast<float2*>(C + (size_t)r0 * ldc + c0)       = make_float2(v0, v1);
            if (r0 + 8 < M) *reinterpret_cast<float2*>(C + (size_t)(r0 + 8) * ldc + c0) = make_float2(v2, v3);
        }
    }
}

// ---------------- CSR build ----------------
__global__ void zero_cnt_k(int* c, int* c2) {
    int i = blockIdx.x * blockDim.x + threadIdx.x;
    if (i < NNODES) { c[i] = 0; c2[i] = 0; }
}
__global__ void count_k(const int* __restrict__ ei, int E, int* __restrict__ cnt) {
    int e = blockIdx.x * blockDim.x + threadIdx.x;
    if (e < E) atomicAdd(&cnt[ei[E + e]], 1);
}
__global__ void scan1_k(const int* __restrict__ cnt, int* __restrict__ ptr,
                        int* __restrict__ bsum) {
    __shared__ int s[256];
    int tid = threadIdx.x;
    int i = blockIdx.x * 256 + tid;
    int v = (i < NNODES) ? cnt[i] : 0;
    s[tid] = v;
    __syncthreads();
    for (int off = 1; off < 256; off <<= 1) {
        int t = (tid >= off) ? s[tid - off] : 0;
        __syncthreads();
        s[tid] += t;
        __syncthreads();
    }
    if (i < NNODES) ptr[i] = s[tid] - v;
    if (tid == 255) bsum[blockIdx.x] = s[255];
}
__global__ void scan2_k(int* __restrict__ bsum, int nb) {
    __shared__ int s[512];
    int tid = threadIdx.x;
    int v = (tid < nb) ? bsum[tid] : 0;
    s[tid] = v;
    __syncthreads();
    for (int off = 1; off < 512; off <<= 1) {
        int t = (tid >= off) ? s[tid - off] : 0;
        __syncthreads();
        s[tid] += t;
        __syncthreads();
    }
    if (tid < nb) bsum[tid] = s[tid] - v;
}
__global__ void scan3_k(int* __restrict__ ptr, const int* __restrict__ bsum, int E) {
    int i = blockIdx.x * 256 + threadIdx.x;
    if (i < NNODES) ptr[i] += bsum[blockIdx.x];
    if (i == 0) ptr[NNODES] = E;
}
__global__ void fill_adj_k(const int* __restrict__ ei, int E,
                           const int* __restrict__ ptr, int* __restrict__ cur,
                           int* __restrict__ adj) {
    int e = blockIdx.x * blockDim.x + threadIdx.x;
    if (e >= E) return;
    int d = ei[E + e];
    int pos = ptr[d] + atomicAdd(&cur[d], 1);
    adj[pos] = ei[e];
}

// ---------------- fused preprocessing: transposes + item-emb copy + folds ----------------
#define PB1 ((DMOV * HID + 255) / 256)           // Ws1^T
#define PB2 (PB1 + (HID * HID + 255) / 256)      // Ws2^T
#define PB3 (PB2 + (NTAGS * 64 + 255) / 256)     // tW1^T
#define PB4 (PB3 + (NITEMS * 16 + 255) / 256)    // iemb copy (float4)
#define PB5 (PB4 + (DMOV * 8 + 255) / 256)       // fold Ws1/as1
#define PB6 (PB5 + (DMOV * 8 + 255) / 256)       // fold Wd1/ad1
#define PGRID (PB6 + 1)                          // +1 block: fold2

__global__ void prep_k(const float* __restrict__ Ws1, const float* __restrict__ Ws2,
                       const float* __restrict__ tW1, const float* __restrict__ iemb,
                       const float* __restrict__ Wd1,
                       const float* __restrict__ as1, const float* __restrict__ ad1,
                       const float* __restrict__ Wd2,
                       const float* __restrict__ as2, const float* __restrict__ ad2,
                       float* __restrict__ bt1, float* __restrict__ bt2,
                       float* __restrict__ btt, float* __restrict__ xmov,
                       float* __restrict__ fold1, float* __restrict__ fold2) {
    int b = blockIdx.x, tid = threadIdx.x;
    if (b < PB1) {
        int i = b * 256 + tid;
        if (i < DMOV * HID) {
            int k = i / HID, n = i - k * HID;
            bt1[(size_t)n * DMOV + k] = tf32r(Ws1[i]);
        }
    } else if (b < PB2) {
        int i = (b - PB1) * 256 + tid;
        if (i < HID * HID) {
            int k = i / HID, n = i - k * HID;
            bt2[(size_t)n * HID + k] = tf32r(Ws2[i]);
        }
    } else if (b < PB3) {
        int i = (b - PB2) * 256 + tid;
        if (i < NTAGS * 64) {
            int k = i / 64, n = i - k * 64;
            btt[(size_t)n * NTAGS + k] = tf32r(tW1[i]);
        }
    } else if (b < PB4) {
        int i = (b - PB3) * 256 + tid;   // float4 index
        if (i < NITEMS * 16) {
            int r = i >> 4, c4 = (i & 15) * 4;
            *reinterpret_cast<float4*>(xmov + (size_t)r * DMOV + c4) =
                reinterpret_cast<const float4*>(iemb)[i];
        }
    } else if (b < PB5) {
        int idx = (b - PB4) * 256 + tid;
        if (idx < DMOV * 8) {
            int k = idx / 8, h = idx & 7;
            float s = 0.f;
            for (int c = 0; c < 32; c++) s += Ws1[(size_t)k * HID + h * 32 + c] * as1[h * 32 + c];
            fold1[k * 16 + h] = s;
        }
    } else if (b < PB6) {
        int idx = (b - PB5) * 256 + tid;
        if (idx < DMOV * 8) {
            int k = idx / 8, h = idx & 7;
            float s = 0.f;
            for (int c = 0; c < 32; c++) s += Wd1[(size_t)k * HID + h * 32 + c] * ad1[h * 32 + c];
            fold1[k * 16 + 8 + h] = s;
        }
    } else {
        int k = tid;   // 256 threads, k in [0,HID)
        float s0 = 0.f, s1 = 0.f;
        for (int c = 0; c < HID; c++) {
            s0 += Ws2[(size_t)k * HID + c] * as2[c];
            s1 += Wd2[(size_t)k * HID + c] * ad2[c];
        }
        fold2[k * 2 + 0] = s0;
        fold2[k * 2 + 1] = s1;
    }
}

// ---------------- fused layer-1 logits (users + movies) ----------------
__global__ void logits_all_k(const float* __restrict__ uemb, const float* __restrict__ xmov,
                             const float* __restrict__ fold1, float* __restrict__ al) {
    __shared__ float sf[DMOV * 16];
    for (int i = threadIdx.x; i < DMOV * 16; i += 256) sf[i] = fold1[i];
    __syncthreads();
    int warp = (blockIdx.x * 256 + threadIdx.x) >> 5;
    int lane = threadIdx.x & 31;
    if (warp >= NNODES) return;
    const float* xr;
    int K;
    if (warp < NUSERS) { xr = uemb + (size_t)warp * 64; K = 64; }
    else               { xr = xmov + (size_t)(warp - NUSERS) * DMOV; K = DMOV; }
    float acc[16];
    #pragma unroll
    for (int h = 0; h < 16; h++) acc[h] = 0.f;
    for (int k = lane; k < K; k += 32) {
        float xv = xr[k];
        #pragma unroll
        for (int h = 0; h < 16; h++) acc[h] += xv * sf[k * 16 + h];
    }
    #pragma unroll
    for (int h = 0; h < 16; h++)
        #pragma unroll
        for (int o = 16; o > 0; o >>= 1) acc[h] += __shfl_xor_sync(0xffffffffu, acc[h], o);
    if (lane == 0) {
        #pragma unroll
        for (int h = 0; h < 16; h++) al[(size_t)warp * 16 + h] = acc[h];
    }
}

// ---------------- FFMA2 GEMM for tiny MLPs ----------------
template <int BM, int BN, int TM, int TN, int ACT, int CVT>
__global__ void __launch_bounds__(256)
gemm2_k(const float* __restrict__ A, int lda,
        const float* __restrict__ B, int ldb,
        float* __restrict__ C, int ldc,
        int M, int N, int K, const float* __restrict__ bias) {
    constexpr int BK  = 16;
    constexpr int SAS = BM + 4;
    constexpr int NA  = (BM * BK) / (4 * 256);
    constexpr int NB  = (BK * BN) / (4 * 256);
    constexpr int TNP = TN / 2;

    __shared__ float sA[2][BK * SAS];
    __shared__ float sB[2][BK * BN];

    const int tid = threadIdx.x;
    const int tx = tid % (BN / TN), ty = tid / (BN / TN);
    const int row0 = blockIdx.y * BM, col0 = blockIdx.x * BN;

    unsigned long long acc[TM][TNP];
    #pragma unroll
    for (int i = 0; i < TM; i++)
        #pragma unroll
        for (int j = 0; j < TNP; j++) acc[i][j] = 0ULL;

    const int nt = (K + BK - 1) / BK;
    float4 pa[NA], pb[NB];

    auto loadA = [&](int k0) {
        #pragma unroll
        for (int i = 0; i < NA; i++) {
            int idx = tid + i * 256;
            int row = idx >> 2, kv = (idx & 3) * 4;
            int gm = row0 + row, gk = k0 + kv;
            float4 v = {0.f, 0.f, 0.f, 0.f};
            if (gm < M && gk < K) v = *reinterpret_cast<const float4*>(A + (size_t)gm * lda + gk);
            pa[i] = v;
        }
    };
    auto loadB = [&](int k0) {
        #pragma unroll
        for (int i = 0; i < NB; i++) {
            int idx = tid + i * 256;
            int kr = idx / (BN / 4), nv = (idx % (BN / 4)) * 4;
            int gk = k0 + kr;
            float4 v = {0.f, 0.f, 0.f, 0.f};
            if (gk < K) v = *reinterpret_cast<const float4*>(B + (size_t)gk * ldb + col0 + nv);
            pb[i] = v;
        }
    };
    auto stage = [&](int buf) {
        #pragma unroll
        for (int i = 0; i < NA; i++) {
            int idx = tid + i * 256;
            int row = idx >> 2, kv = (idx & 3) * 4;
            float* p = &sA[buf][0];
            p[(kv + 0) * SAS + row] = pa[i].x;
            p[(kv + 1) * SAS + row] = pa[i].y;
            p[(kv + 2) * SAS + row] = pa[i].z;
            p[(kv + 3) * SAS + row] = pa[i].w;
        }
        #pragma unroll
        for (int i = 0; i < NB; i++) {
            int idx = tid + i * 256;
            int kr = idx / (BN / 4), nv = (idx % (BN / 4)) * 4;
            *reinterpret_cast<float4*>(&sB[buf][kr * BN + nv]) = pb[i];
        }
    };

    loadA(0); loadB(0);
    stage(0);
    __syncthreads();

    for (int t = 0; t < nt; t++) {
        int buf = t & 1;
        if (t + 1 < nt) { loadA((t + 1) * BK); loadB((t + 1) * BK); }
        #pragma unroll
        for (int kk = 0; kk < BK; kk++) {
            float a[TM];
            #pragma unroll
            for (int i = 0; i < TM; i += 4)
                *reinterpret_cast<float4*>(&a[i]) =
                    *reinterpret_cast<const float4*>(&sA[buf][kk * SAS + ty * TM + i]);
            unsigned long long bp[TNP];
            const unsigned long long* sBp =
                reinterpret_cast<const unsigned long long*>(&sB[buf][kk * BN + tx * TN]);
            #pragma unroll
            for (int j = 0; j < TNP; j++) bp[j] = sBp[j];
            #pragma unroll
            for (int i = 0; i < TM; i++) {
                unsigned long long ap;
                asm("mov.b64 %0, {%1, %1};" : "=l"(ap) : "f"(a[i]));
                #pragma unroll
                for (int j = 0; j < TNP; j++)
                    asm("fma.rn.f32x2 %0, %1, %2, %0;"
                        : "+l"(acc[i][j]) : "l"(ap), "l"(bp[j]));
            }
        }
        if (t + 1 < nt) stage(buf ^ 1);
        __syncthreads();
    }

    #pragma unroll
    for (int i = 0; i < TM; i++) {
        int gm = row0 + ty * TM + i;
        if (gm >= M) continue;
        #pragma unroll
        for (int j = 0; j < TNP; j++) {
            float lo, hi;
            asm("mov.b64 {%0, %1}, %2;" : "=f"(lo), "=f"(hi) : "l"(acc[i][j]));
            int gn = col0 + tx * TN + 2 * j;
            if (bias) { lo += bias[gn]; hi += bias[gn + 1]; }
            if (ACT == 1) { lo = fmaxf(lo, 0.f); hi = fmaxf(hi, 0.f); }
            if (CVT == 1) { lo = tf32r(lo); hi = tf32r(hi); }
            C[(size_t)gm * ldc + gn]     = lo;
            C[(size_t)gm * ldc + gn + 1] = hi;
        }
    }
}

// ---------------- layer-1 CSR aggregate (chunked over dst range) ----------------
__global__ void agg1_k(const int* __restrict__ adj, const int* __restrict__ ptr,
                       const float* __restrict__ al, const float* __restrict__ hs,
                       const float* __restrict__ b1, const float* __restrict__ fold2,
                       float* __restrict__ out1, float* __restrict__ al2,
                       int dst0, int ndst) {
    __shared__ float  sb[HID];
    __shared__ float2 sf[HID];
    int tid = threadIdx.x, lane = tid & 31;
    for (int i = tid; i < HID; i += blockDim.x) {
        sb[i] = b1[i];
        sf[i] = reinterpret_cast<const float2*>(fold2)[i];
    }
    __syncthreads();
    int rel = (blockIdx.x * blockDim.x + tid) >> 5;
    if (rel >= ndst) return;
    int dst = dst0 + rel;
    int beg = ptr[dst], end = ptr[dst + 1];
    float ald = (lane < 8) ? al[(size_t)dst * 16 + 8 + lane] : 0.f;
    float4 a0 = {0.f, 0.f, 0.f, 0.f}, a1 = {0.f, 0.f, 0.f, 0.f};
    float ss = 0.f;
    for (int p = beg; p < end; p++) {
        int src = adj[p];
        float w = 0.f;
        if (lane < 8) {
            float v = al[(size_t)src * 16 + lane] + ald;
            v = (v > 0.f) ? v : 0.2f * v;
            w = __expf(v);
            ss += w;
        }
        float w0 = __shfl_sync(0xffffffffu, w, lane >> 3);
        float w1 = __shfl_sync(0xffffffffu, w, 4 + (lane >> 3));
        const float4* hv = reinterpret_cast<const float4*>(hs + (size_t)src * HID);
        float4 h0 = hv[lane], h1 = hv[32 + lane];
        a0.x += w0 * h0.x; a0.y += w0 * h0.y; a0.z += w0 * h0.z; a0.w += w0 * h0.w;
        a1.x += w1 * h1.x; a1.y += w1 * h1.y; a1.z += w1 * h1.z; a1.w += w1 * h1.w;
    }
    float s0 = __shfl_sync(0xffffffffu, ss, lane >> 3);
    float s1 = __shfl_sync(0xffffffffu, ss, 4 + (lane >> 3));
    float i0 = __fdividef(1.f, s0 + 1e-16f);
    float i1 = __fdividef(1.f, s1 + 1e-16f);
    int c0 = lane * 4, c1 = 128 + lane * 4;
    float4 v0, v1;
    v0.x = a0.x * i0 + sb[c0 + 0];
    v0.y = a0.y * i0 + sb[c0 + 1];
    v0.z = a0.z * i0 + sb[c0 + 2];
    v0.w = a0.w * i0 + sb[c0 + 3];
    v1.x = a1.x * i1 + sb[c1 + 0];
    v1.y = a1.y * i1 + sb[c1 + 1];
    v1.z = a1.z * i1 + sb[c1 + 2];
    v1.w = a1.w * i1 + sb[c1 + 3];
    v0.x = tf32r(v0.x > 0.f ? v0.x : expm1f(v0.x));
    v0.y = tf32r(v0.y > 0.f ? v0.y : expm1f(v0.y));
    v0.z = tf32r(v0.z > 0.f ? v0.z : expm1f(v0.z));
    v0.w = tf32r(v0.w > 0.f ? v0.w : expm1f(v0.w));
    v1.x = tf32r(v1.x > 0.f ? v1.x : expm1f(v1.x));
    v1.y = tf32r(v1.y > 0.f ? v1.y : expm1f(v1.y));
    v1.z = tf32r(v1.z > 0.f ? v1.z : expm1f(v1.z));
    v1.w = tf32r(v1.w > 0.f ? v1.w : expm1f(v1.w));
    float4* ov = reinterpret_cast<float4*>(out1 + (size_t)dst * HID);
    ov[lane] = v0;
    ov[32 + lane] = v1;
    float d0 = v0.x * sf[c0 + 0].x + v0.y * sf[c0 + 1].x + v0.z * sf[c0 + 2].x + v0.w * sf[c0 + 3].x
             + v1.x * sf[c1 + 0].x + v1.y * sf[c1 + 1].x + v1.z * sf[c1 + 2].x + v1.w * sf[c1 + 3].x;
    float d1 = v0.x * sf[c0 + 0].y + v0.y * sf[c0 + 1].y + v0.z * sf[c0 + 2].y + v0.w * sf[c0 + 3].y
             + v1.x * sf[c1 + 0].y + v1.y * sf[c1 + 1].y + v1.z * sf[c1 + 2].y + v1.w * sf[c1 + 3].y;
    #pragma unroll
    for (int o = 16; o > 0; o >>= 1) {
        d0 += __shfl_xor_sync(0xffffffffu, d0, o);
        d1 += __shfl_xor_sync(0xffffffffu, d1, o);
    }
    if (lane == 0) {
        al2[(size_t)dst * 2 + 0] = d0;
        al2[(size_t)dst * 2 + 1] = d1;
    }
}

// ---------------- layer-2 CSR aggregate ----------------
__global__ void agg2_k(const int* __restrict__ adj, const int* __restrict__ ptr,
                       const float* __restrict__ al2, const float* __restrict__ hs,
                       const float* __restrict__ b2, float* __restrict__ dout,
                       int out_size) {
    __shared__ float sb[HID];
    int tid = threadIdx.x, lane = tid & 31;
    for (int i = tid; i < HID; i += blockDim.x) sb[i] = b2[i];
    __syncthreads();
    int dst = (blockIdx.x * blockDim.x + tid) >> 5;
    if (dst >= NNODES) return;
    int beg = ptr[dst], end = ptr[dst + 1];
    float ald = al2[(size_t)dst * 2 + 1];
    float4 a0 = {0.f, 0.f, 0.f, 0.f}, a1 = {0.f, 0.f, 0.f, 0.f};
    float ss = 0.f;
    for (int p = beg; p < end; p++) {
        int src = adj[p];
        float w = 0.f;
        if (lane == 0) {
            float v = al2[(size_t)src * 2] + ald;
            v = (v > 0.f) ? v : 0.2f * v;
            w = __expf(v);
        }
        w = __shfl_sync(0xffffffffu, w, 0);
        ss += w;
        const float4* hv = reinterpret_cast<const float4*>(hs + (size_t)src * HID);
        float4 h0 = hv[lane], h1 = hv[32 + lane];
        a0.x += w * h0.x; a0.y += w * h0.y; a0.z += w * h0.z; a0.w += w * h0.w;
        a1.x += w * h1.x; a1.y += w * h1.y; a1.z += w * h1.z; a1.w += w * h1.w;
    }
    float inv = __fdividef(1.f, ss + 1e-16f);
    int c0 = lane * 4, c1 = 128 + lane * 4;
    float4 v0, v1;
    v0.x = a0.x * inv + sb[c0 + 0];
    v0.y = a0.y * inv + sb[c0 + 1];
    v0.z = a0.z * inv + sb[c0 + 2];
    v0.w = a0.w * inv + sb[c0 + 3];
    v1.x = a1.x * inv + sb[c1 + 0];
    v1.y = a1.y * inv + sb[c1 + 1];
    v1.z = a1.z * inv + sb[c1 + 2];
    v1.w = a1.w * inv + sb[c1 + 3];
    float4* ov = reinterpret_cast<float4*>(dout + (size_t)dst * HID);
    ov[lane] = v0;
    ov[32 + lane] = v1;
    if (dst == 0 && lane == 0) {
        dout[out_size - 3] = 0.0f;
        dout[out_size - 2] = (float)NUSERS;
        dout[out_size - 1] = (float)NNODES;
    }
}

// ---------------- streams (created at static-init time, before harness baseline) ----------------
struct StreamPack {
    cudaStream_t s1 = nullptr, s2 = nullptr;
    cudaEvent_t ev0 = nullptr, evPrep = nullptr, evXmov = nullptr;
    cudaEvent_t evCSR = nullptr, evU = nullptr, evL = nullptr;
    cudaEvent_t evA[NCHUNK] = {}, evG[NCHUNK] = {};
    bool ok = false;
    StreamPack() {
        ok = (cudaStreamCreateWithFlags(&s1, cudaStreamNonBlocking) == cudaSuccess) &&
             (cudaStreamCreateWithFlags(&s2, cudaStreamNonBlocking) == cudaSuccess) &&
             (cudaEventCreateWithFlags(&ev0,    cudaEventDisableTiming) == cudaSuccess) &&
             (cudaEventCreateWithFlags(&evPrep, cudaEventDisableTiming) == cudaSuccess) &&
             (cudaEventCreateWithFlags(&evXmov, cudaEventDisableTiming) == cudaSuccess) &&
             (cudaEventCreateWithFlags(&evCSR,  cudaEventDisableTiming) == cudaSuccess) &&
             (cudaEventCreateWithFlags(&evU,    cudaEventDisableTiming) == cudaSuccess) &&
             (cudaEventCreateWithFlags(&evL,    cudaEventDisableTiming) == cudaSuccess);
        for (int i = 0; i < NCHUNK && ok; i++) {
            ok = (cudaEventCreateWithFlags(&evA[i], cudaEventDisableTiming) == cudaSuccess) &&
                 (cudaEventCreateWithFlags(&evG[i], cudaEventDisableTiming) == cudaSuccess);
        }
    }
};
static StreamPack g_sp;

// ---------------- launch ----------------
static inline float* symaddr(const void* s) {
    void* p = nullptr;
    cudaGetSymbolAddress(&p, s);
    return (float*)p;
}
static inline int* symaddri(const void* s) {
    void* p = nullptr;
    cudaGetSymbolAddress(&p, s);
    return (int*)p;
}

extern "C" void kernel_launch(void* const* d_in, const int* in_sizes, int n_in,
                              void* d_out, int out_size) {
    const float* mov_x = (const float*)d_in[2];
    const int*   ei    = (const int*)d_in[3];
    const float* uemb  = (const float*)d_in[4];
    const float* iemb  = (const float*)d_in[5];
    const float* gW1 = (const float*)d_in[6];  const float* gb1 = (const float*)d_in[7];
    const float* gW2 = (const float*)d_in[8];  const float* gb2 = (const float*)d_in[9];
    const float* tW1 = (const float*)d_in[10]; const float* tb1 = (const float*)d_in[11];
    const float* tW2 = (const float*)d_in[12]; const float* tb2 = (const float*)d_in[13];
    const float* Ws1 = (const float*)d_in[14]; const float* Wd1 = (const float*)d_in[15];
    const float* as1 = (const float*)d_in[16]; const float* ad1 = (const float*)d_in[17];
    const float* b1  = (const float*)d_in[18];
    const float* Ws2 = (const float*)d_in[19]; const float* Wd2 = (const float*)d_in[20];
    const float* as2 = (const float*)d_in[21]; const float* ad2 = (const float*)d_in[22];
    const float* b2  = (const float*)d_in[23];
    const int E = in_sizes[3] / 2;
    float* out = (float*)d_out;

    float* xmov = symaddr(g_xmov);
    float* th   = symaddr(g_th);
    float* gh   = symaddr(g_gh);
    float* hs1  = symaddr(g_hs1);
    float* out1 = symaddr(g_out1);
    float* hs2  = symaddr(g_hs2);
    float* al1  = symaddr(g_al1);
    float* al2  = symaddr(g_al2);
    float* fold1 = symaddr(g_fold1);
    float* fold2 = symaddr(g_fold2);
    float* bt1  = symaddr(g_bt1);
    float* bt2  = symaddr(g_bt2);
    float* btt  = symaddr(g_btt);
    int* cnt  = symaddri(g_cnt);
    int* cur  = symaddri(g_cur);
    int* ptr  = symaddri(g_ptr);
    int* bsum = symaddri(g_bsum);
    int* adj  = symaddri(g_adj);

    auto nb = [](int n) { return (n + 255) / 256; };

    const int SM128 = 2 * (128 + 128) * 36 * 4;   // 73728 -> 3 CTAs/SM
    const int SM64  = 2 * (128 + 64)  * 36 * 4;   // 55296
    cudaFuncSetAttribute(mma_gemm_k<128, 64, 32, 0>, cudaFuncAttributeMaxDynamicSharedMemorySize, SM128);
    cudaFuncSetAttribute(mma_gemm_k<64, 32, 32, 1>,  cudaFuncAttributeMaxDynamicSharedMemorySize, SM64);

    const bool use_streams = g_sp.ok;
    cudaStream_t s0 = 0;
    cudaStream_t s1 = use_streams ? g_sp.s1 : s0;
    cudaStream_t s2 = use_streams ? g_sp.s2 : s0;

    if (use_streams) cudaEventRecord(g_sp.ev0, s0);

    // --- s0: preprocessing ---
    prep_k<<<PGRID, 256, 0, s0>>>(Ws1, Ws2, tW1, iemb, Wd1, as1, ad1, Wd2, as2, ad2,
                                  bt1, bt2, btt, xmov, fold1, fold2);
    if (use_streams) cudaEventRecord(g_sp.evPrep, s0);

    // --- s1: CSR build chain ---
    if (use_streams) cudaStreamWaitEvent(s1, g_sp.ev0, 0);
    zero_cnt_k<<<NBLK, 256, 0, s1>>>(cnt, cur);
    count_k<<<nb(E), 256, 0, s1>>>(ei, E, cnt);
    scan1_k<<<NBLK, 256, 0, s1>>>(cnt, ptr, bsum);
    scan2_k<<<1, 512, 0, s1>>>(bsum, NBLK);
    scan3_k<<<NBLK, 256, 0, s1>>>(ptr, bsum, E);
    fill_adj_k<<<nb(E), 256, 0, s1>>>(ei, E, ptr, cur, adj);
    if (use_streams) cudaEventRecord(g_sp.evCSR, s1);

    // --- s2: user hs1 GEMM ---
    if (use_streams) cudaStreamWaitEvent(s2, g_sp.evPrep, 0);
    mma_gemm_k<128, 64, 32, 0><<<dim3(2, (NUSERS + 127) / 128), 256, SM128, s2>>>(
        uemb, 64, bt1, DMOV, hs1, HID, NUSERS, 64, nullptr);
    if (use_streams) cudaEventRecord(g_sp.evU, s2);

    // --- s0: movie feature pipeline ---
    mma_gemm_k<64, 32, 32, 1><<<dim3(1, (NITEMS + 127) / 128), 256, SM64, s0>>>(
        mov_x + NGEN, MOVLD, btt, NTAGS, th, 64, NITEMS, NTAGS, tb1);
    {
        dim3 g(1, (NITEMS + 127) / 128);
        gemm2_k<128, 64, 8, 4, 1, 0><<<g, 256, 0, s0>>>(mov_x, MOVLD, gW1, 64, gh, 64, NITEMS, 64, NGEN, gb1);
        gemm2_k<128, 64, 8, 4, 0, 1><<<g, 256, 0, s0>>>(gh, 64, gW2, 64, xmov + 64, DMOV, NITEMS, 64, 64, gb2);
        gemm2_k<128, 64, 8, 4, 0, 1><<<g, 256, 0, s0>>>(th, 64, tW2, 64, xmov + 128, DMOV, NITEMS, 64, 64, tb2);
    }
    if (use_streams) cudaEventRecord(g_sp.evXmov, s0);

    // --- s2: layer-1 logits ---
    if (use_streams) cudaStreamWaitEvent(s2, g_sp.evXmov, 0);
    logits_all_k<<<nb(NNODES * 32), 256, 0, s2>>>(uemb, xmov, fold1, al1);
    if (use_streams) cudaEventRecord(g_sp.evL, s2);

    // --- s0: movie hs1 GEMM ---
    mma_gemm_k<128, 64, 32, 0><<<dim3(2, (NITEMS + 127) / 128), 256, SM128, s0>>>(
        xmov, DMOV, bt1, DMOV, hs1 + (size_t)NUSERS * HID, HID, NITEMS, DMOV, nullptr);

    // --- join before agg1 ---
    if (use_streams) {
        cudaStreamWaitEvent(s0, g_sp.evCSR, 0);
        cudaStreamWaitEvent(s0, g_sp.evU, 0);
        cudaStreamWaitEvent(s0, g_sp.evL, 0);
    }

    // --- pipelined agg1 (s0) -> hs2 GEMM chunks (s2) ---
    for (int c = 0; c < NCHUNK; c++) {
        int d0 = c * CHUNK;
        agg1_k<<<nb(CHUNK * 32), 256, 0, s0>>>(adj, ptr, al1, hs1, b1, fold2, out1, al2,
                                               d0, CHUNK);
        if (use_streams) {
            cudaEventRecord(g_sp.evA[c], s0);
            cudaStreamWaitEvent(s2, g_sp.evA[c], 0);
        }
        mma_gemm_k<128, 64, 32, 0><<<dim3(2, (CHUNK + 127) / 128), 256, SM128,
                                     use_streams ? s2 : s0>>>(
            out1 + (size_t)d0 * HID, HID, bt2, HID,
            hs2 + (size_t)d0 * HID, HID, CHUNK, HID, nullptr);
        if (use_streams) cudaEventRecord(g_sp.evG[c], s2);
    }
    if (use_streams)
        for (int c = 0; c < NCHUNK; c++) cudaStreamWaitEvent(s0, g_sp.evG[c], 0);

    agg2_k<<<nb(NNODES * 32), 256, 0, s0>>>(adj, ptr, al2, hs2, b2, out, out_size);
}

// round 14
// speedup vs baseline: 1.0114x; 1.0114x over previous
#include <cuda_runtime.h>
#include <cstdint>

#define NUSERS 100000
#define NITEMS 20000
#define NNODES 120000
#define DMOV   192
#define HID    256
#define NGEN   20
#define NTAGS  1128
#define MOVLD  1148
#define ETOT   400000
#define NBLK   ((NNODES + 255) / 256)

// ---------------- scratch (static device globals; no allocation) ----------------
__device__ __align__(16) float g_xmov[NITEMS * DMOV];    // item_emb | g | t
__device__ __align__(16) float g_gh  [NITEMS * 64];
__device__ __align__(16) float g_th  [NITEMS * 64];
__device__ __align__(16) float g_hs1 [NNODES * HID];
__device__ __align__(16) float g_out1[NNODES * HID];
__device__ __align__(16) float g_hs2 [NNODES * HID];
__device__ __align__(16) float g_al1 [NNODES * 16];      // [al_s(8) | al_d(8)]
__device__ __align__(16) float g_al2 [NNODES * 2];
__device__ __align__(16) float g_fold1[DMOV * 16];
__device__ __align__(16) float g_fold2[HID * 2];
__device__ __align__(16) float g_bt1 [HID * DMOV];       // Ws1^T tf32
__device__ __align__(16) float g_bt2 [HID * HID];        // Ws2^T tf32
__device__ __align__(16) float g_btt [64 * NTAGS];       // tW1^T tf32
// CSR
__device__ int g_cnt[NNODES];
__device__ int g_cur[NNODES];
__device__ int g_ptr[NNODES + 1];
__device__ int g_bsum[512];
__device__ int g_adj[ETOT];

// ---------------- helpers ----------------
__device__ __forceinline__ uint32_t f2tf32(float f) {
    uint32_t u;
    asm("cvt.rna.tf32.f32 %0, %1;" : "=r"(u) : "f"(f));
    return u;
}
__device__ __forceinline__ float tf32r(float f) { return __uint_as_float(f2tf32(f)); }
__device__ __forceinline__ uint32_t smaddr(const void* p) {
    uint32_t a;
    asm("{ .reg .u64 t; cvta.to.shared.u64 t, %1; cvt.u32.u64 %0, t; }" : "=r"(a) : "l"(p));
    return a;
}
#define CP_ASYNC16(dst, src, sz) \
    asm volatile("cp.async.cg.shared.global [%0], [%1], 16, %2;" \
                 :: "r"(dst), "l"(src), "r"(sz) : "memory")
#define CP_COMMIT() asm volatile("cp.async.commit_group;" ::: "memory")
#define CP_WAIT(n)  asm volatile("cp.async.wait_group %0;" :: "n"(n) : "memory")

// ---------------- tf32 mma.sync GEMM with cp.async staging (2-stage, 3 CTA/SM) ----------------
template <int BN, int WM, int WN, int ACT>
__global__ void __launch_bounds__(256)
mma_gemm_k(const float* __restrict__ A, int lda,
           const float* __restrict__ Bt, int ldb,
           float* __restrict__ C, int ldc,
           int M, int K, const float* __restrict__ bias) {
    constexpr int BM = 128, BK = 32;
    constexpr int SK = BK + 4;
    constexpr int MT = WM / 16, NT = WN / 8;
    constexpr int NWN = BN / WN;
    constexpr int NA = BM * BK / (4 * 256);
    constexpr int NB = BN * BK / (4 * 256);

    extern __shared__ float sm[];
    float* sAb[2]; float* sBb[2];
    sAb[0] = sm;
    sBb[0] = sm + BM * SK;
    sAb[1] = sm + (BM + BN) * SK;
    sBb[1] = sAb[1] + BM * SK;
    const uint32_t sA0 = smaddr(sAb[0]), sB0 = smaddr(sBb[0]);
    const uint32_t sA1 = smaddr(sAb[1]), sB1 = smaddr(sBb[1]);

    const int tid = threadIdx.x, wid = tid >> 5, lane = tid & 31;
    const int wm = wid / NWN, wn = wid % NWN;
    const int group = lane >> 2, qid = lane & 3;
    const int row0 = blockIdx.y * BM, col0 = blockIdx.x * BN;

    float acc[MT][NT][4];
    #pragma unroll
    for (int i = 0; i < MT; i++)
        #pragma unroll
        for (int j = 0; j < NT; j++)
            #pragma unroll
            for (int t = 0; t < 4; t++) acc[i][j][t] = 0.0f;

    const int nt = (K + BK - 1) / BK;

    auto issue = [&](int t) {
        const int k0 = t * BK;
        const uint32_t dA = (t & 1) ? sA1 : sA0;
        const uint32_t dB = (t & 1) ? sB1 : sB0;
        #pragma unroll
        for (int i = 0; i < NA; i++) {
            int idx = tid + i * 256;
            int row = idx >> 3, kv = (idx & 7) * 4;
            int gm = row0 + row, gk = k0 + kv;
            uint32_t sz = (gm < M && gk < K) ? 16u : 0u;
            CP_ASYNC16(dA + (uint32_t)(row * SK + kv) * 4,
                       A + (size_t)gm * lda + gk, sz);
        }
        #pragma unroll
        for (int i = 0; i < NB; i++) {
            int idx = tid + i * 256;
            int row = idx >> 3, kv = (idx & 7) * 4;
            int gk = k0 + kv;
            uint32_t sz = (gk < K) ? 16u : 0u;
            CP_ASYNC16(dB + (uint32_t)(row * SK + kv) * 4,
                       Bt + (size_t)(col0 + row) * ldb + gk, sz);
        }
    };

    issue(0); CP_COMMIT();

    for (int t = 0; t < nt; t++) {
        if (t + 1 < nt) { issue(t + 1); CP_COMMIT(); CP_WAIT(1); }
        else            { CP_WAIT(0); }
        __syncthreads();
        const float* sA = (t & 1) ? sAb[1] : sAb[0];
        const float* sB = (t & 1) ? sBb[1] : sBb[0];
        #pragma unroll
        for (int ks = 0; ks < 4; ks++) {
            const int koff = ks * 8;
            uint32_t af[MT][4], bf[NT][2];
            #pragma unroll
            for (int i = 0; i < MT; i++) {
                const float* p = sA + (wm * WM + i * 16) * SK + koff;
                af[i][0] = __float_as_uint(p[group * SK + qid]);
                af[i][1] = __float_as_uint(p[(group + 8) * SK + qid]);
                af[i][2] = __float_as_uint(p[group * SK + qid + 4]);
                af[i][3] = __float_as_uint(p[(group + 8) * SK + qid + 4]);
            }
            #pragma unroll
            for (int j = 0; j < NT; j++) {
                const float* p = sB + (wn * WN + j * 8 + group) * SK + koff;
                bf[j][0] = __float_as_uint(p[qid]);
                bf[j][1] = __float_as_uint(p[qid + 4]);
            }
            #pragma unroll
            for (int i = 0; i < MT; i++)
                #pragma unroll
                for (int j = 0; j < NT; j++)
                    asm volatile(
                        "mma.sync.aligned.m16n8k8.row.col.f32.tf32.tf32.f32 "
                        "{%0,%1,%2,%3}, {%4,%5,%6,%7}, {%8,%9}, {%0,%1,%2,%3};"
                        : "+f"(acc[i][j][0]), "+f"(acc[i][j][1]),
                          "+f"(acc[i][j][2]), "+f"(acc[i][j][3])
                        : "r"(af[i][0]), "r"(af[i][1]), "r"(af[i][2]), "r"(af[i][3]),
                          "r"(bf[j][0]), "r"(bf[j][1]));
        }
        __syncthreads();
    }

    #pragma unroll
    for (int i = 0; i < MT; i++) {
        #pragma unroll
        for (int j = 0; j < NT; j++) {
            int r0 = row0 + wm * WM + i * 16 + group;
            int c0 = col0 + wn * WN + j * 8 + qid * 2;
            float b0 = bias ? bias[c0] : 0.f, b1 = bias ? bias[c0 + 1] : 0.f;
            float v0 = acc[i][j][0] + b0, v1 = acc[i][j][1] + b1;
            float v2 = acc[i][j][2] + b0, v3 = acc[i][j][3] + b1;
            if (ACT == 1) {
                v0 = fmaxf(v0, 0.f); v1 = fmaxf(v1, 0.f);
                v2 = fmaxf(v2, 0.f); v3 = fmaxf(v3, 0.f);
            }
            if (r0 < M)     *reinterpret_cast<float2*>(C + (size_t)r0 * ldc + c0)       = make_float2(v0, v1);
            if (r0 + 8 < M) *reinterpret_cast<float2*>(C + (size_t)(r0 + 8) * ldc + c0) = make_float2(v2, v3);
        }
    }
}

// ---------------- CSR build ----------------
__global__ void zero_cnt_k(int* c, int* c2) {
    int i = blockIdx.x * blockDim.x + threadIdx.x;
    if (i < NNODES) { c[i] = 0; c2[i] = 0; }
}
__global__ void count_k(const int* __restrict__ ei, int E, int* __restrict__ cnt) {
    int e = blockIdx.x * blockDim.x + threadIdx.x;
    if (e < E) atomicAdd(&cnt[ei[E + e]], 1);
}
__global__ void scan1_k(const int* __restrict__ cnt, int* __restrict__ ptr,
                        int* __restrict__ bsum) {
    __shared__ int s[256];
    int tid = threadIdx.x;
    int i = blockIdx.x * 256 + tid;
    int v = (i < NNODES) ? cnt[i] : 0;
    s[tid] = v;
    __syncthreads();
    for (int off = 1; off < 256; off <<= 1) {
        int t = (tid >= off) ? s[tid - off] : 0;
        __syncthreads();
        s[tid] += t;
        __syncthreads();
    }
    if (i < NNODES) ptr[i] = s[tid] - v;
    if (tid == 255) bsum[blockIdx.x] = s[255];
}
__global__ void scan2_k(int* __restrict__ bsum, int nb) {
    __shared__ int s[512];
    int tid = threadIdx.x;
    int v = (tid < nb) ? bsum[tid] : 0;
    s[tid] = v;
    __syncthreads();
    for (int off = 1; off < 512; off <<= 1) {
        int t = (tid >= off) ? s[tid - off] : 0;
        __syncthreads();
        s[tid] += t;
        __syncthreads();
    }
    if (tid < nb) bsum[tid] = s[tid] - v;
}
__global__ void scan3_k(int* __restrict__ ptr, const int* __restrict__ bsum, int E) {
    int i = blockIdx.x * 256 + threadIdx.x;
    if (i < NNODES) ptr[i] += bsum[blockIdx.x];
    if (i == 0) ptr[NNODES] = E;
}
__global__ void fill_adj_k(const int* __restrict__ ei, int E,
                           const int* __restrict__ ptr, int* __restrict__ cur,
                           int* __restrict__ adj) {
    int e = blockIdx.x * blockDim.x + threadIdx.x;
    if (e >= E) return;
    int d = ei[E + e];
    int pos = ptr[d] + atomicAdd(&cur[d], 1);
    adj[pos] = ei[e];
}
__global__ void noop_k() {}

// ---------------- fused preprocessing ----------------
#define PB1 ((DMOV * HID + 255) / 256)
#define PB2 (PB1 + (HID * HID + 255) / 256)
#define PB3 (PB2 + (NTAGS * 64 + 255) / 256)
#define PB4 (PB3 + (NITEMS * 16 + 255) / 256)
#define PB5 (PB4 + (DMOV * 8 + 255) / 256)
#define PB6 (PB5 + (DMOV * 8 + 255) / 256)
#define PGRID (PB6 + 1)

__global__ void prep_k(const float* __restrict__ Ws1, const float* __restrict__ Ws2,
                       const float* __restrict__ tW1, const float* __restrict__ iemb,
                       const float* __restrict__ Wd1,
                       const float* __restrict__ as1, const float* __restrict__ ad1,
                       const float* __restrict__ Wd2,
                       const float* __restrict__ as2, const float* __restrict__ ad2,
                       float* __restrict__ bt1, float* __restrict__ bt2,
                       float* __restrict__ btt, float* __restrict__ xmov,
                       float* __restrict__ fold1, float* __restrict__ fold2) {
    int b = blockIdx.x, tid = threadIdx.x;
    if (b < PB1) {
        int i = b * 256 + tid;
        if (i < DMOV * HID) {
            int k = i / HID, n = i - k * HID;
            bt1[(size_t)n * DMOV + k] = tf32r(Ws1[i]);
        }
    } else if (b < PB2) {
        int i = (b - PB1) * 256 + tid;
        if (i < HID * HID) {
            int k = i / HID, n = i - k * HID;
            bt2[(size_t)n * HID + k] = tf32r(Ws2[i]);
        }
    } else if (b < PB3) {
        int i = (b - PB2) * 256 + tid;
        if (i < NTAGS * 64) {
            int k = i / 64, n = i - k * 64;
            btt[(size_t)n * NTAGS + k] = tf32r(tW1[i]);
        }
    } else if (b < PB4) {
        int i = (b - PB3) * 256 + tid;
        if (i < NITEMS * 16) {
            int r = i >> 4, c4 = (i & 15) * 4;
            *reinterpret_cast<float4*>(xmov + (size_t)r * DMOV + c4) =
                reinterpret_cast<const float4*>(iemb)[i];
        }
    } else if (b < PB5) {
        int idx = (b - PB4) * 256 + tid;
        if (idx < DMOV * 8) {
            int k = idx / 8, h = idx & 7;
            float s = 0.f;
            for (int c = 0; c < 32; c++) s += Ws1[(size_t)k * HID + h * 32 + c] * as1[h * 32 + c];
            fold1[k * 16 + h] = s;
        }
    } else if (b < PB6) {
        int idx = (b - PB5) * 256 + tid;
        if (idx < DMOV * 8) {
            int k = idx / 8, h = idx & 7;
            float s = 0.f;
            for (int c = 0; c < 32; c++) s += Wd1[(size_t)k * HID + h * 32 + c] * ad1[h * 32 + c];
            fold1[k * 16 + 8 + h] = s;
        }
    } else {
        int k = tid;
        float s0 = 0.f, s1 = 0.f;
        for (int c = 0; c < HID; c++) {
            s0 += Ws2[(size_t)k * HID + c] * as2[c];
            s1 += Wd2[(size_t)k * HID + c] * ad2[c];
        }
        fold2[k * 2 + 0] = s0;
        fold2[k * 2 + 1] = s1;
    }
}

// ---------------- fused layer-1 logits ----------------
__global__ void logits_all_k(const float* __restrict__ uemb, const float* __restrict__ xmov,
                             const float* __restrict__ fold1, float* __restrict__ al) {
    __shared__ float sf[DMOV * 16];
    for (int i = threadIdx.x; i < DMOV * 16; i += 256) sf[i] = fold1[i];
    __syncthreads();
    int warp = (blockIdx.x * 256 + threadIdx.x) >> 5;
    int lane = threadIdx.x & 31;
    if (warp >= NNODES) return;
    const float* xr;
    int K;
    if (warp < NUSERS) { xr = uemb + (size_t)warp * 64; K = 64; }
    else               { xr = xmov + (size_t)(warp - NUSERS) * DMOV; K = DMOV; }
    float acc[16];
    #pragma unroll
    for (int h = 0; h < 16; h++) acc[h] = 0.f;
    for (int k = lane; k < K; k += 32) {
        float xv = xr[k];
        #pragma unroll
        for (int h = 0; h < 16; h++) acc[h] += xv * sf[k * 16 + h];
    }
    #pragma unroll
    for (int h = 0; h < 16; h++)
        #pragma unroll
        for (int o = 16; o > 0; o >>= 1) acc[h] += __shfl_xor_sync(0xffffffffu, acc[h], o);
    if (lane == 0) {
        #pragma unroll
        for (int h = 0; h < 16; h++) al[(size_t)warp * 16 + h] = acc[h];
    }
}

// ---------------- FFMA2 GEMM for tiny MLPs ----------------
template <int BM, int BN, int TM, int TN, int ACT, int CVT>
__global__ void __launch_bounds__(256)
gemm2_k(const float* __restrict__ A, int lda,
        const float* __restrict__ B, int ldb,
        float* __restrict__ C, int ldc,
        int M, int N, int K, const float* __restrict__ bias) {
    constexpr int BK  = 16;
    constexpr int SAS = BM + 4;
    constexpr int NA  = (BM * BK) / (4 * 256);
    constexpr int NB  = (BK * BN) / (4 * 256);
    constexpr int TNP = TN / 2;

    __shared__ float sA[2][BK * SAS];
    __shared__ float sB[2][BK * BN];

    const int tid = threadIdx.x;
    const int tx = tid % (BN / TN), ty = tid / (BN / TN);
    const int row0 = blockIdx.y * BM, col0 = blockIdx.x * BN;

    unsigned long long acc[TM][TNP];
    #pragma unroll
    for (int i = 0; i < TM; i++)
        #pragma unroll
        for (int j = 0; j < TNP; j++) acc[i][j] = 0ULL;

    const int nt = (K + BK - 1) / BK;
    float4 pa[NA], pb[NB];

    auto loadA = [&](int k0) {
        #pragma unroll
        for (int i = 0; i < NA; i++) {
            int idx = tid + i * 256;
            int row = idx >> 2, kv = (idx & 3) * 4;
            int gm = row0 + row, gk = k0 + kv;
            float4 v = {0.f, 0.f, 0.f, 0.f};
            if (gm < M && gk < K) v = *reinterpret_cast<const float4*>(A + (size_t)gm * lda + gk);
            pa[i] = v;
        }
    };
    auto loadB = [&](int k0) {
        #pragma unroll
        for (int i = 0; i < NB; i++) {
            int idx = tid + i * 256;
            int kr = idx / (BN / 4), nv = (idx % (BN / 4)) * 4;
            int gk = k0 + kr;
            float4 v = {0.f, 0.f, 0.f, 0.f};
            if (gk < K) v = *reinterpret_cast<const float4*>(B + (size_t)gk * ldb + col0 + nv);
            pb[i] = v;
        }
    };
    auto stage = [&](int buf) {
        #pragma unroll
        for (int i = 0; i < NA; i++) {
            int idx = tid + i * 256;
            int row = idx >> 2, kv = (idx & 3) * 4;
            float* p = &sA[buf][0];
            p[(kv + 0) * SAS + row] = pa[i].x;
            p[(kv + 1) * SAS + row] = pa[i].y;
            p[(kv + 2) * SAS + row] = pa[i].z;
            p[(kv + 3) * SAS + row] = pa[i].w;
        }
        #pragma unroll
        for (int i = 0; i < NB; i++) {
            int idx = tid + i * 256;
            int kr = idx / (BN / 4), nv = (idx % (BN / 4)) * 4;
            *reinterpret_cast<float4*>(&sB[buf][kr * BN + nv]) = pb[i];
        }
    };

    loadA(0); loadB(0);
    stage(0);
    __syncthreads();

    for (int t = 0; t < nt; t++) {
        int buf = t & 1;
        if (t + 1 < nt) { loadA((t + 1) * BK); loadB((t + 1) * BK); }
        #pragma unroll
        for (int kk = 0; kk < BK; kk++) {
            float a[TM];
            #pragma unroll
            for (int i = 0; i < TM; i += 4)
                *reinterpret_cast<float4*>(&a[i]) =
                    *reinterpret_cast<const float4*>(&sA[buf][kk * SAS + ty * TM + i]);
            unsigned long long bp[TNP];
            const unsigned long long* sBp =
                reinterpret_cast<const unsigned long long*>(&sB[buf][kk * BN + tx * TN]);
            #pragma unroll
            for (int j = 0; j < TNP; j++) bp[j] = sBp[j];
            #pragma unroll
            for (int i = 0; i < TM; i++) {
                unsigned long long ap;
                asm("mov.b64 %0, {%1, %1};" : "=l"(ap) : "f"(a[i]));
                #pragma unroll
                for (int j = 0; j < TNP; j++)
                    asm("fma.rn.f32x2 %0, %1, %2, %0;"
                        : "+l"(acc[i][j]) : "l"(ap), "l"(bp[j]));
            }
        }
        if (t + 1 < nt) stage(buf ^ 1);
        __syncthreads();
    }

    #pragma unroll
    for (int i = 0; i < TM; i++) {
        int gm = row0 + ty * TM + i;
        if (gm >= M) continue;
        #pragma unroll
        for (int j = 0; j < TNP; j++) {
            float lo, hi;
            asm("mov.b64 {%0, %1}, %2;" : "=f"(lo), "=f"(hi) : "l"(acc[i][j]));
            int gn = col0 + tx * TN + 2 * j;
            if (bias) { lo += bias[gn]; hi += bias[gn + 1]; }
            if (ACT == 1) { lo = fmaxf(lo, 0.f); hi = fmaxf(hi, 0.f); }
            if (CVT == 1) { lo = tf32r(lo); hi = tf32r(hi); }
            C[(size_t)gm * ldc + gn]     = lo;
            C[(size_t)gm * ldc + gn + 1] = hi;
        }
    }
}

// ---------------- layer-1 CSR aggregate (dst range) ----------------
__global__ void agg1_k(const int* __restrict__ adj, const int* __restrict__ ptr,
                       const float* __restrict__ al, const float* __restrict__ hs,
                       const float* __restrict__ b1, const float* __restrict__ fold2,
                       float* __restrict__ out1, float* __restrict__ al2,
                       int dst0, int ndst) {
    __shared__ float  sb[HID];
    __shared__ float2 sf[HID];
    int tid = threadIdx.x, lane = tid & 31;
    for (int i = tid; i < HID; i += blockDim.x) {
        sb[i] = b1[i];
        sf[i] = reinterpret_cast<const float2*>(fold2)[i];
    }
    __syncthreads();
    int rel = (blockIdx.x * blockDim.x + tid) >> 5;
    if (rel >= ndst) return;
    int dst = dst0 + rel;
    int beg = ptr[dst], end = ptr[dst + 1];
    float ald = (lane < 8) ? al[(size_t)dst * 16 + 8 + lane] : 0.f;
    float4 a0 = {0.f, 0.f, 0.f, 0.f}, a1 = {0.f, 0.f, 0.f, 0.f};
    float ss = 0.f;
    for (int p = beg; p < end; p++) {
        int src = adj[p];
        float w = 0.f;
        if (lane < 8) {
            float v = al[(size_t)src * 16 + lane] + ald;
            v = (v > 0.f) ? v : 0.2f * v;
            w = __expf(v);
            ss += w;
        }
        float w0 = __shfl_sync(0xffffffffu, w, lane >> 3);
        float w1 = __shfl_sync(0xffffffffu, w, 4 + (lane >> 3));
        const float4* hv = reinterpret_cast<const float4*>(hs + (size_t)src * HID);
        float4 h0 = hv[lane], h1 = hv[32 + lane];
        a0.x += w0 * h0.x; a0.y += w0 * h0.y; a0.z += w0 * h0.z; a0.w += w0 * h0.w;
        a1.x += w1 * h1.x; a1.y += w1 * h1.y; a1.z += w1 * h1.z; a1.w += w1 * h1.w;
    }
    float s0 = __shfl_sync(0xffffffffu, ss, lane >> 3);
    float s1 = __shfl_sync(0xffffffffu, ss, 4 + (lane >> 3));
    float i0 = __fdividef(1.f, s0 + 1e-16f);
    float i1 = __fdividef(1.f, s1 + 1e-16f);
    int c0 = lane * 4, c1 = 128 + lane * 4;
    float4 v0, v1;
    v0.x = a0.x * i0 + sb[c0 + 0];
    v0.y = a0.y * i0 + sb[c0 + 1];
    v0.z = a0.z * i0 + sb[c0 + 2];
    v0.w = a0.w * i0 + sb[c0 + 3];
    v1.x = a1.x * i1 + sb[c1 + 0];
    v1.y = a1.y * i1 + sb[c1 + 1];
    v1.z = a1.z * i1 + sb[c1 + 2];
    v1.w = a1.w * i1 + sb[c1 + 3];
    v0.x = tf32r(v0.x > 0.f ? v0.x : expm1f(v0.x));
    v0.y = tf32r(v0.y > 0.f ? v0.y : expm1f(v0.y));
    v0.z = tf32r(v0.z > 0.f ? v0.z : expm1f(v0.z));
    v0.w = tf32r(v0.w > 0.f ? v0.w : expm1f(v0.w));
    v1.x = tf32r(v1.x > 0.f ? v1.x : expm1f(v1.x));
    v1.y = tf32r(v1.y > 0.f ? v1.y : expm1f(v1.y));
    v1.z = tf32r(v1.z > 0.f ? v1.z : expm1f(v1.z));
    v1.w = tf32r(v1.w > 0.f ? v1.w : expm1f(v1.w));
    float4* ov = reinterpret_cast<float4*>(out1 + (size_t)dst * HID);
    ov[lane] = v0;
    ov[32 + lane] = v1;
    float d0 = v0.x * sf[c0 + 0].x + v0.y * sf[c0 + 1].x + v0.z * sf[c0 + 2].x + v0.w * sf[c0 + 3].x
             + v1.x * sf[c1 + 0].x + v1.y * sf[c1 + 1].x + v1.z * sf[c1 + 2].x + v1.w * sf[c1 + 3].x;
    float d1 = v0.x * sf[c0 + 0].y + v0.y * sf[c0 + 1].y + v0.z * sf[c0 + 2].y + v0.w * sf[c0 + 3].y
             + v1.x * sf[c1 + 0].y + v1.y * sf[c1 + 1].y + v1.z * sf[c1 + 2].y + v1.w * sf[c1 + 3].y;
    #pragma unroll
    for (int o = 16; o > 0; o >>= 1) {
        d0 += __shfl_xor_sync(0xffffffffu, d0, o);
        d1 += __shfl_xor_sync(0xffffffffu, d1, o);
    }
    if (lane == 0) {
        al2[(size_t)dst * 2 + 0] = d0;
        al2[(size_t)dst * 2 + 1] = d1;
    }
}

// ---------------- layer-2 CSR aggregate (dst range) ----------------
__global__ void agg2_k(const int* __restrict__ adj, const int* __restrict__ ptr,
                       const float* __restrict__ al2, const float* __restrict__ hs,
                       const float* __restrict__ b2, float* __restrict__ dout,
                       int out_size, int dst0, int ndst) {
    __shared__ float sb[HID];
    int tid = threadIdx.x, lane = tid & 31;
    for (int i = tid; i < HID; i += blockDim.x) sb[i] = b2[i];
    __syncthreads();
    int rel = (blockIdx.x * blockDim.x + tid) >> 5;
    if (rel >= ndst) return;
    int dst = dst0 + rel;
    int beg = ptr[dst], end = ptr[dst + 1];
    float ald = al2[(size_t)dst * 2 + 1];
    float4 a0 = {0.f, 0.f, 0.f, 0.f}, a1 = {0.f, 0.f, 0.f, 0.f};
    float ss = 0.f;
    for (int p = beg; p < end; p++) {
        int src = adj[p];
        float w = 0.f;
        if (lane == 0) {
            float v = al2[(size_t)src * 2] + ald;
            v = (v > 0.f) ? v : 0.2f * v;
            w = __expf(v);
        }
        w = __shfl_sync(0xffffffffu, w, 0);
        ss += w;
        const float4* hv = reinterpret_cast<const float4*>(hs + (size_t)src * HID);
        float4 h0 = hv[lane], h1 = hv[32 + lane];
        a0.x += w * h0.x; a0.y += w * h0.y; a0.z += w * h0.z; a0.w += w * h0.w;
        a1.x += w * h1.x; a1.y += w * h1.y; a1.z += w * h1.z; a1.w += w * h1.w;
    }
    float inv = __fdividef(1.f, ss + 1e-16f);
    int c0 = lane * 4, c1 = 128 + lane * 4;
    float4 v0, v1;
    v0.x = a0.x * inv + sb[c0 + 0];
    v0.y = a0.y * inv + sb[c0 + 1];
    v0.z = a0.z * inv + sb[c0 + 2];
    v0.w = a0.w * inv + sb[c0 + 3];
    v1.x = a1.x * inv + sb[c1 + 0];
    v1.y = a1.y * inv + sb[c1 + 1];
    v1.z = a1.z * inv + sb[c1 + 2];
    v1.w = a1.w * inv + sb[c1 + 3];
    float4* ov = reinterpret_cast<float4*>(dout + (size_t)dst * HID);
    ov[lane] = v0;
    ov[32 + lane] = v1;
    if (dst == 0 && lane == 0) {
        dout[out_size - 3] = 0.0f;
        dout[out_size - 2] = (float)NUSERS;
        dout[out_size - 1] = (float)NNODES;
    }
}

// ---------------- streams (created at static-init time) ----------------
struct StreamPack {
    cudaStream_t s1 = nullptr, s2 = nullptr;
    cudaEvent_t ev0 = nullptr, evPrep = nullptr, evXmov = nullptr;
    cudaEvent_t evCSR = nullptr, evHU = nullptr, evL = nullptr;
    cudaEvent_t evA1U = nullptr, evG2U = nullptr, evG2M = nullptr, evOU = nullptr;
    bool ok = false;
    StreamPack() {
        ok = (cudaStreamCreateWithFlags(&s1, cudaStreamNonBlocking) == cudaSuccess) &&
             (cudaStreamCreateWithFlags(&s2, cudaStreamNonBlocking) == cudaSuccess) &&
             (cudaEventCreateWithFlags(&ev0,    cudaEventDisableTiming) == cudaSuccess) &&
             (cudaEventCreateWithFlags(&evPrep, cudaEventDisableTiming) == cudaSuccess) &&
             (cudaEventCreateWithFlags(&evXmov, cudaEventDisableTiming) == cudaSuccess) &&
             (cudaEventCreateWithFlags(&evCSR,  cudaEventDisableTiming) == cudaSuccess) &&
             (cudaEventCreateWithFlags(&evHU,   cudaEventDisableTiming) == cudaSuccess) &&
             (cudaEventCreateWithFlags(&evL,    cudaEventDisableTiming) == cudaSuccess) &&
             (cudaEventCreateWithFlags(&evA1U,  cudaEventDisableTiming) == cudaSuccess) &&
             (cudaEventCreateWithFlags(&evG2U,  cudaEventDisableTiming) == cudaSuccess) &&
             (cudaEventCreateWithFlags(&evG2M,  cudaEventDisableTiming) == cudaSuccess) &&
             (cudaEventCreateWithFlags(&evOU,   cudaEventDisableTiming) == cudaSuccess);
    }
};
static StreamPack g_sp;

// ---------------- launch ----------------
static inline float* symaddr(const void* s) {
    void* p = nullptr;
    cudaGetSymbolAddress(&p, s);
    return (float*)p;
}
static inline int* symaddri(const void* s) {
    void* p = nullptr;
    cudaGetSymbolAddress(&p, s);
    return (int*)p;
}

extern "C" void kernel_launch(void* const* d_in, const int* in_sizes, int n_in,
                              void* d_out, int out_size) {
    const float* mov_x = (const float*)d_in[2];
    const int*   ei    = (const int*)d_in[3];
    const float* uemb  = (const float*)d_in[4];
    const float* iemb  = (const float*)d_in[5];
    const float* gW1 = (const float*)d_in[6];  const float* gb1 = (const float*)d_in[7];
    const float* gW2 = (const float*)d_in[8];  const float* gb2 = (const float*)d_in[9];
    const float* tW1 = (const float*)d_in[10]; const float* tb1 = (const float*)d_in[11];
    const float* tW2 = (const float*)d_in[12]; const float* tb2 = (const float*)d_in[13];
    const float* Ws1 = (const float*)d_in[14]; const float* Wd1 = (const float*)d_in[15];
    const float* as1 = (const float*)d_in[16]; const float* ad1 = (const float*)d_in[17];
    const float* b1  = (const float*)d_in[18];
    const float* Ws2 = (const float*)d_in[19]; const float* Wd2 = (const float*)d_in[20];
    const float* as2 = (const float*)d_in[21]; const float* ad2 = (const float*)d_in[22];
    const float* b2  = (const float*)d_in[23];
    const int E = in_sizes[3] / 2;
    float* out = (float*)d_out;

    float* xmov = symaddr(g_xmov);
    float* th   = symaddr(g_th);
    float* gh   = symaddr(g_gh);
    float* hs1  = symaddr(g_hs1);
    float* out1 = symaddr(g_out1);
    float* hs2  = symaddr(g_hs2);
    float* al1  = symaddr(g_al1);
    float* al2  = symaddr(g_al2);
    float* fold1 = symaddr(g_fold1);
    float* fold2 = symaddr(g_fold2);
    float* bt1  = symaddr(g_bt1);
    float* bt2  = symaddr(g_bt2);
    float* btt  = symaddr(g_btt);
    int* cnt  = symaddri(g_cnt);
    int* cur  = symaddri(g_cur);
    int* ptr  = symaddri(g_ptr);
    int* bsum = symaddri(g_bsum);
    int* adj  = symaddri(g_adj);

    auto nb = [](int n) { return (n + 255) / 256; };

    const int SM128 = 2 * (128 + 128) * 36 * 4;   // 73728 -> 3 CTAs/SM
    const int SM64  = 2 * (128 + 64)  * 36 * 4;   // 55296
    cudaFuncSetAttribute(mma_gemm_k<128, 64, 32, 0>, cudaFuncAttributeMaxDynamicSharedMemorySize, SM128);
    cudaFuncSetAttribute(mma_gemm_k<64, 32, 32, 1>,  cudaFuncAttributeMaxDynamicSharedMemorySize, SM64);

    const bool use_streams = g_sp.ok;
    cudaStream_t s0 = 0;
    cudaStream_t s1 = use_streams ? g_sp.s1 : s0;
    cudaStream_t s2 = use_streams ? g_sp.s2 : s0;

    if (use_streams) cudaEventRecord(g_sp.ev0, s0);

    // --- s0: preprocessing ---
    prep_k<<<PGRID, 256, 0, s0>>>(Ws1, Ws2, tW1, iemb, Wd1, as1, ad1, Wd2, as2, ad2,
                                  bt1, bt2, btt, xmov, fold1, fold2);
    if (use_streams) cudaEventRecord(g_sp.evPrep, s0);

    // --- s1: CSR build chain ---
    if (use_streams) cudaStreamWaitEvent(s1, g_sp.ev0, 0);
    zero_cnt_k<<<NBLK, 256, 0, s1>>>(cnt, cur);
    count_k<<<nb(E), 256, 0, s1>>>(ei, E, cnt);
    scan1_k<<<NBLK, 256, 0, s1>>>(cnt, ptr, bsum);
    scan2_k<<<1, 512, 0, s1>>>(bsum, NBLK);
    scan3_k<<<NBLK, 256, 0, s1>>>(ptr, bsum, E);
    fill_adj_k<<<nb(E), 256, 0, s1>>>(ei, E, ptr, cur, adj);
    if (use_streams) cudaEventRecord(g_sp.evCSR, s1);

    // --- s2: user hs1 GEMM ---
    if (use_streams) cudaStreamWaitEvent(s2, g_sp.evPrep, 0);
    mma_gemm_k<128, 64, 32, 0><<<dim3(2, (NUSERS + 127) / 128), 256, SM128, s2>>>(
        uemb, 64, bt1, DMOV, hs1, HID, NUSERS, 64, nullptr);
    if (use_streams) cudaEventRecord(g_sp.evHU, s2);

    // --- s0: movie feature pipeline ---
    mma_gemm_k<64, 32, 32, 1><<<dim3(1, (NITEMS + 127) / 128), 256, SM64, s0>>>(
        mov_x + NGEN, MOVLD, btt, NTAGS, th, 64, NITEMS, NTAGS, tb1);
    {
        dim3 g(1, (NITEMS + 127) / 128);
        gemm2_k<128, 64, 8, 4, 1, 0><<<g, 256, 0, s0>>>(mov_x, MOVLD, gW1, 64, gh, 64, NITEMS, 64, NGEN, gb1);
        gemm2_k<128, 64, 8, 4, 0, 1><<<g, 256, 0, s0>>>(gh, 64, gW2, 64, xmov + 64, DMOV, NITEMS, 64, 64, gb2);
        gemm2_k<128, 64, 8, 4, 0, 1><<<g, 256, 0, s0>>>(th, 64, tW2, 64, xmov + 128, DMOV, NITEMS, 64, 64, tb2);
    }
    if (use_streams) cudaEventRecord(g_sp.evXmov, s0);

    // --- s2: layer-1 logits ---
    if (use_streams) cudaStreamWaitEvent(s2, g_sp.evXmov, 0);
    logits_all_k<<<nb(NNODES * 32), 256, 0, s2>>>(uemb, xmov, fold1, al1);
    if (use_streams) cudaEventRecord(g_sp.evL, s2);

    // --- s0: movie hs1 GEMM ---
    mma_gemm_k<128, 64, 32, 0><<<dim3(2, (NITEMS + 127) / 128), 256, SM128, s0>>>(
        xmov, DMOV, bt1, DMOV, hs1 + (size_t)NUSERS * HID, HID, NITEMS, DMOV, nullptr);

    // --- s0: agg1 over USER dsts (srcs are movies -> needs only hs1_movies) ---
    if (use_streams) {
        cudaStreamWaitEvent(s0, g_sp.evCSR, 0);
        cudaStreamWaitEvent(s0, g_sp.evL, 0);
    }
    agg1_k<<<nb(NUSERS * 32), 256, 0, s0>>>(adj, ptr, al1, hs1, b1, fold2, out1, al2,
                                            0, NUSERS);
    if (use_streams) cudaEventRecord(g_sp.evA1U, s0);

    // --- s2: hs2 GEMM over user rows (concurrent with agg1_movies) ---
    if (use_streams) cudaStreamWaitEvent(s2, g_sp.evA1U, 0);
    mma_gemm_k<128, 64, 32, 0><<<dim3(2, (NUSERS + 127) / 128), 256, SM128, s2>>>(
        out1, HID, bt2, HID, hs2, HID, NUSERS, HID, nullptr);
    if (use_streams) cudaEventRecord(g_sp.evG2U, s2);

    // --- s0: agg1 over MOVIE dsts (srcs are users -> needs hs1_users) ---
    if (use_streams) cudaStreamWaitEvent(s0, g_sp.evHU, 0);
    agg1_k<<<nb(NITEMS * 32), 256, 0, s0>>>(adj, ptr, al1, hs1, b1, fold2, out1, al2,
                                            NUSERS, NITEMS);

    // --- s0: hs2 GEMM over movie rows ---
    mma_gemm_k<128, 64, 32, 0><<<dim3(2, (NITEMS + 127) / 128), 256, SM128, s0>>>(
        out1 + (size_t)NUSERS * HID, HID, bt2, HID,
        hs2 + (size_t)NUSERS * HID, HID, NITEMS, HID, nullptr);
    if (use_streams) cudaEventRecord(g_sp.evG2M, s0);

    // --- s2: agg2 over USER dsts (srcs are movies -> needs hs2_movies) ---
    if (use_streams) cudaStreamWaitEvent(s2, g_sp.evG2M, 0);
    agg2_k<<<nb(NUSERS * 32), 256, 0, s2>>>(adj, ptr, al2, hs2, b2, out, out_size,
                                            0, NUSERS);
    if (use_streams) cudaEventRecord(g_sp.evOU, s2);

    // --- s0: agg2 over MOVIE dsts (srcs are users -> needs hs2_users) ---
    if (use_streams) cudaStreamWaitEvent(s0, g_sp.evG2U, 0);
    agg2_k<<<nb(NITEMS * 32), 256, 0, s0>>>(adj, ptr, al2, hs2, b2, out, out_size,
                                            NUSERS, NITEMS);

    // --- join all forked work back into s0 ---
    if (use_streams) {
        cudaStreamWaitEvent(s0, g_sp.evOU, 0);
        noop_k<<<1, 1, 0, s0>>>();
    }
}

// round 15
// speedup vs baseline: 1.0272x; 1.0156x over previous
#include <cuda_runtime.h>
#include <cstdint>

#define NUSERS 100000
#define NITEMS 20000
#define NNODES 120000
#define DMOV   192
#define HID    256
#define NGEN   20
#define NTAGS  1128
#define MOVLD  1148
#define ETOT   400000
#define NBLK   ((NNODES + 255) / 256)

// ---------------- scratch (static device globals; no allocation) ----------------
__device__ __align__(16) float g_xmov[NITEMS * DMOV];    // item_emb | g | t
__device__ __align__(16) float g_gh  [NITEMS * 64];
__device__ __align__(16) float g_th  [NITEMS * 64];
__device__ __align__(16) float g_hs1 [NNODES * HID];
__device__ __align__(16) float g_out1[NNODES * HID];
__device__ __align__(16) float g_hs2 [NNODES * HID];
__device__ __align__(16) float g_al1 [NNODES * 16];      // [al_s(8) | al_d(8)]
__device__ __align__(16) float g_al2 [NNODES * 2];
__device__ __align__(16) float g_fold1[DMOV * 16];
__device__ __align__(16) float g_fold2[HID * 2];
__device__ __align__(16) float g_bt1 [HID * DMOV];       // Ws1^T tf32
__device__ __align__(16) float g_bt2 [HID * HID];        // Ws2^T tf32
__device__ __align__(16) float g_btt [64 * NTAGS];       // tW1^T tf32
// CSR
__device__ int g_cnt[NNODES];
__device__ int g_cur[NNODES];
__device__ int g_ptr[NNODES + 1];
__device__ int g_bsum[512];
__device__ int g_adj[ETOT];

// ---------------- helpers ----------------
__device__ __forceinline__ uint32_t f2tf32(float f) {
    uint32_t u;
    asm("cvt.rna.tf32.f32 %0, %1;" : "=r"(u) : "f"(f));
    return u;
}
__device__ __forceinline__ float tf32r(float f) { return __uint_as_float(f2tf32(f)); }
__device__ __forceinline__ uint32_t smaddr(const void* p) {
    uint32_t a;
    asm("{ .reg .u64 t; cvta.to.shared.u64 t, %1; cvt.u32.u64 %0, t; }" : "=r"(a) : "l"(p));
    return a;
}
#define CP_ASYNC16(dst, src, sz) \
    asm volatile("cp.async.cg.shared.global [%0], [%1], 16, %2;" \
                 :: "r"(dst), "l"(src), "r"(sz) : "memory")
#define CP_COMMIT() asm volatile("cp.async.commit_group;" ::: "memory")
#define CP_WAIT(n)  asm volatile("cp.async.wait_group %0;" :: "n"(n) : "memory")

// ---------------- tf32 mma.sync GEMM with cp.async staging (2-stage) ----------------
template <int BN, int WM, int WN, int ACT>
__global__ void __launch_bounds__(256)
mma_gemm_k(const float* __restrict__ A, int lda,
           const float* __restrict__ Bt, int ldb,
           float* __restrict__ C, int ldc,
           int M, int K, const float* __restrict__ bias) {
    constexpr int BM = 128, BK = 32;
    constexpr int SK = BK + 4;
    constexpr int MT = WM / 16, NT = WN / 8;
    constexpr int NWN = BN / WN;
    constexpr int NA = BM * BK / (4 * 256);
    constexpr int NB = BN * BK / (4 * 256);

    extern __shared__ float sm[];
    float* sAb[2]; float* sBb[2];
    sAb[0] = sm;
    sBb[0] = sm + BM * SK;
    sAb[1] = sm + (BM + BN) * SK;
    sBb[1] = sAb[1] + BM * SK;
    const uint32_t sA0 = smaddr(sAb[0]), sB0 = smaddr(sBb[0]);
    const uint32_t sA1 = smaddr(sAb[1]), sB1 = smaddr(sBb[1]);

    const int tid = threadIdx.x, wid = tid >> 5, lane = tid & 31;
    const int wm = wid / NWN, wn = wid % NWN;
    const int group = lane >> 2, qid = lane & 3;
    const int row0 = blockIdx.y * BM, col0 = blockIdx.x * BN;

    float acc[MT][NT][4];
    #pragma unroll
    for (int i = 0; i < MT; i++)
        #pragma unroll
        for (int j = 0; j < NT; j++)
            #pragma unroll
            for (int t = 0; t < 4; t++) acc[i][j][t] = 0.0f;

    const int nt = (K + BK - 1) / BK;

    auto issue = [&](int t) {
        const int k0 = t * BK;
        const uint32_t dA = (t & 1) ? sA1 : sA0;
        const uint32_t dB = (t & 1) ? sB1 : sB0;
        #pragma unroll
        for (int i = 0; i < NA; i++) {
            int idx = tid + i * 256;
            int row = idx >> 3, kv = (idx & 7) * 4;
            int gm = row0 + row, gk = k0 + kv;
            uint32_t sz = (gm < M && gk < K) ? 16u : 0u;
            CP_ASYNC16(dA + (uint32_t)(row * SK + kv) * 4,
                       A + (size_t)gm * lda + gk, sz);
        }
        #pragma unroll
        for (int i = 0; i < NB; i++) {
            int idx = tid + i * 256;
            int row = idx >> 3, kv = (idx & 7) * 4;
            int gk = k0 + kv;
            uint32_t sz = (gk < K) ? 16u : 0u;
            CP_ASYNC16(dB + (uint32_t)(row * SK + kv) * 4,
                       Bt + (size_t)(col0 + row) * ldb + gk, sz);
        }
    };

    issue(0); CP_COMMIT();

    for (int t = 0; t < nt; t++) {
        if (t + 1 < nt) { issue(t + 1); CP_COMMIT(); CP_WAIT(1); }
        else            { CP_WAIT(0); }
        __syncthreads();
        const float* sA = (t & 1) ? sAb[1] : sAb[0];
        const float* sB = (t & 1) ? sBb[1] : sBb[0];
        #pragma unroll
        for (int ks = 0; ks < 4; ks++) {
            const int koff = ks * 8;
            uint32_t af[MT][4], bf[NT][2];
            #pragma unroll
            for (int i = 0; i < MT; i++) {
                const float* p = sA + (wm * WM + i * 16) * SK + koff;
                af[i][0] = __float_as_uint(p[group * SK + qid]);
                af[i][1] = __float_as_uint(p[(group + 8) * SK + qid]);
                af[i][2] = __float_as_uint(p[group * SK + qid + 4]);
                af[i][3] = __float_as_uint(p[(group + 8) * SK + qid + 4]);
            }
            #pragma unroll
            for (int j = 0; j < NT; j++) {
                const float* p = sB + (wn * WN + j * 8 + group) * SK + koff;
                bf[j][0] = __float_as_uint(p[qid]);
                bf[j][1] = __float_as_uint(p[qid + 4]);
            }
            #pragma unroll
            for (int i = 0; i < MT; i++)
                #pragma unroll
                for (int j = 0; j < NT; j++)
                    asm volatile(
                        "mma.sync.aligned.m16n8k8.row.col.f32.tf32.tf32.f32 "
                        "{%0,%1,%2,%3}, {%4,%5,%6,%7}, {%8,%9}, {%0,%1,%2,%3};"
                        : "+f"(acc[i][j][0]), "+f"(acc[i][j][1]),
                          "+f"(acc[i][j][2]), "+f"(acc[i][j][3])
                        : "r"(af[i][0]), "r"(af[i][1]), "r"(af[i][2]), "r"(af[i][3]),
                          "r"(bf[j][0]), "r"(bf[j][1]));
        }
        __syncthreads();
    }

    #pragma unroll
    for (int i = 0; i < MT; i++) {
        #pragma unroll
        for (int j = 0; j < NT; j++) {
            int r0 = row0 + wm * WM + i * 16 + group;
            int c0 = col0 + wn * WN + j * 8 + qid * 2;
            float b0 = bias ? bias[c0] : 0.f, b1 = bias ? bias[c0 + 1] : 0.f;
            float v0 = acc[i][j][0] + b0, v1 = acc[i][j][1] + b1;
            float v2 = acc[i][j][2] + b0, v3 = acc[i][j][3] + b1;
            if (ACT == 1) {
                v0 = fmaxf(v0, 0.f); v1 = fmaxf(v1, 0.f);
                v2 = fmaxf(v2, 0.f); v3 = fmaxf(v3, 0.f);
            }
            if (r0 < M)     *reinterpret_cast<float2*>(C + (size_t)r0 * ldc + c0)       = make_float2(v0, v1);
            if (r0 + 8 < M) *reinterpret_cast<float2*>(C + (size_t)(r0 + 8) * ldc + c0) = make_float2(v2, v3);
        }
    }
}

// ---------------- CSR build ----------------
__global__ void zero_cnt_k(int* c, int* c2) {
    int i = blockIdx.x * blockDim.x + threadIdx.x;
    if (i < NNODES) { c[i] = 0; c2[i] = 0; }
}
__global__ void count_k(const int* __restrict__ ei, int E, int* __restrict__ cnt) {
    int e = blockIdx.x * blockDim.x + threadIdx.x;
    if (e < E) atomicAdd(&cnt[ei[E + e]], 1);
}
__global__ void scan1_k(const int* __restrict__ cnt, int* __restrict__ ptr,
                        int* __restrict__ bsum) {
    __shared__ int s[256];
    int tid = threadIdx.x;
    int i = blockIdx.x * 256 + tid;
    int v = (i < NNODES) ? cnt[i] : 0;
    s[tid] = v;
    __syncthreads();
    for (int off = 1; off < 256; off <<= 1) {
        int t = (tid >= off) ? s[tid - off] : 0;
        __syncthreads();
        s[tid] += t;
        __syncthreads();
    }
    if (i < NNODES) ptr[i] = s[tid] - v;
    if (tid == 255) bsum[blockIdx.x] = s[255];
}
__global__ void scan2_k(int* __restrict__ bsum, int nb) {
    __shared__ int s[512];
    int tid = threadIdx.x;
    int v = (tid < nb) ? bsum[tid] : 0;
    s[tid] = v;
    __syncthreads();
    for (int off = 1; off < 512; off <<= 1) {
        int t = (tid >= off) ? s[tid - off] : 0;
        __syncthreads();
        s[tid] += t;
        __syncthreads();
    }
    if (tid < nb) bsum[tid] = s[tid] - v;
}
__global__ void scan3_k(int* __restrict__ ptr, const int* __restrict__ bsum, int E) {
    int i = blockIdx.x * 256 + threadIdx.x;
    if (i < NNODES) ptr[i] += bsum[blockIdx.x];
    if (i == 0) ptr[NNODES] = E;
}
__global__ void fill_adj_k(const int* __restrict__ ei, int E,
                           const int* __restrict__ ptr, int* __restrict__ cur,
                           int* __restrict__ adj) {
    int e = blockIdx.x * blockDim.x + threadIdx.x;
    if (e >= E) return;
    int d = ei[E + e];
    int pos = ptr[d] + atomicAdd(&cur[d], 1);
    adj[pos] = ei[e];
}

// ---------------- fused preprocessing ----------------
#define PB1 ((DMOV * HID + 255) / 256)
#define PB2 (PB1 + (HID * HID + 255) / 256)
#define PB3 (PB2 + (NTAGS * 64 + 255) / 256)
#define PB4 (PB3 + (NITEMS * 16 + 255) / 256)
#define PB5 (PB4 + (DMOV * 8 + 255) / 256)
#define PB6 (PB5 + (DMOV * 8 + 255) / 256)
#define PGRID (PB6 + 1)

__global__ void prep_k(const float* __restrict__ Ws1, const float* __restrict__ Ws2,
                       const float* __restrict__ tW1, const float* __restrict__ iemb,
                       const float* __restrict__ Wd1,
                       const float* __restrict__ as1, const float* __restrict__ ad1,
                       const float* __restrict__ Wd2,
                       const float* __restrict__ as2, const float* __restrict__ ad2,
                       float* __restrict__ bt1, float* __restrict__ bt2,
                       float* __restrict__ btt, float* __restrict__ xmov,
                       float* __restrict__ fold1, float* __restrict__ fold2) {
    int b = blockIdx.x, tid = threadIdx.x;
    if (b < PB1) {
        int i = b * 256 + tid;
        if (i < DMOV * HID) {
            int k = i / HID, n = i - k * HID;
            bt1[(size_t)n * DMOV + k] = tf32r(Ws1[i]);
        }
    } else if (b < PB2) {
        int i = (b - PB1) * 256 + tid;
        if (i < HID * HID) {
            int k = i / HID, n = i - k * HID;
            bt2[(size_t)n * HID + k] = tf32r(Ws2[i]);
        }
    } else if (b < PB3) {
        int i = (b - PB2) * 256 + tid;
        if (i < NTAGS * 64) {
            int k = i / 64, n = i - k * 64;
            btt[(size_t)n * NTAGS + k] = tf32r(tW1[i]);
        }
    } else if (b < PB4) {
        int i = (b - PB3) * 256 + tid;
        if (i < NITEMS * 16) {
            int r = i >> 4, c4 = (i & 15) * 4;
            *reinterpret_cast<float4*>(xmov + (size_t)r * DMOV + c4) =
                reinterpret_cast<const float4*>(iemb)[i];
        }
    } else if (b < PB5) {
        int idx = (b - PB4) * 256 + tid;
        if (idx < DMOV * 8) {
            int k = idx / 8, h = idx & 7;
            float s = 0.f;
            for (int c = 0; c < 32; c++) s += Ws1[(size_t)k * HID + h * 32 + c] * as1[h * 32 + c];
            fold1[k * 16 + h] = s;
        }
    } else if (b < PB6) {
        int idx = (b - PB5) * 256 + tid;
        if (idx < DMOV * 8) {
            int k = idx / 8, h = idx & 7;
            float s = 0.f;
            for (int c = 0; c < 32; c++) s += Wd1[(size_t)k * HID + h * 32 + c] * ad1[h * 32 + c];
            fold1[k * 16 + 8 + h] = s;
        }
    } else {
        int k = tid;
        float s0 = 0.f, s1 = 0.f;
        for (int c = 0; c < HID; c++) {
            s0 += Ws2[(size_t)k * HID + c] * as2[c];
            s1 += Wd2[(size_t)k * HID + c] * ad2[c];
        }
        fold2[k * 2 + 0] = s0;
        fold2[k * 2 + 1] = s1;
    }
}

// ---------------- fused layer-1 logits ----------------
__global__ void logits_all_k(const float* __restrict__ uemb, const float* __restrict__ xmov,
                             const float* __restrict__ fold1, float* __restrict__ al) {
    __shared__ float sf[DMOV * 16];
    for (int i = threadIdx.x; i < DMOV * 16; i += 256) sf[i] = fold1[i];
    __syncthreads();
    int warp = (blockIdx.x * 256 + threadIdx.x) >> 5;
    int lane = threadIdx.x & 31;
    if (warp >= NNODES) return;
    const float* xr;
    int K;
    if (warp < NUSERS) { xr = uemb + (size_t)warp * 64; K = 64; }
    else               { xr = xmov + (size_t)(warp - NUSERS) * DMOV; K = DMOV; }
    float acc[16];
    #pragma unroll
    for (int h = 0; h < 16; h++) acc[h] = 0.f;
    for (int k = lane; k < K; k += 32) {
        float xv = xr[k];
        #pragma unroll
        for (int h = 0; h < 16; h++) acc[h] += xv * sf[k * 16 + h];
    }
    #pragma unroll
    for (int h = 0; h < 16; h++)
        #pragma unroll
        for (int o = 16; o > 0; o >>= 1) acc[h] += __shfl_xor_sync(0xffffffffu, acc[h], o);
    if (lane == 0) {
        #pragma unroll
        for (int h = 0; h < 16; h++) al[(size_t)warp * 16 + h] = acc[h];
    }
}

// ---------------- FFMA2 GEMM for tiny MLPs ----------------
template <int BM, int BN, int TM, int TN, int ACT, int CVT>
__global__ void __launch_bounds__(256)
gemm2_k(const float* __restrict__ A, int lda,
        const float* __restrict__ B, int ldb,
        float* __restrict__ C, int ldc,
        int M, int N, int K, const float* __restrict__ bias) {
    constexpr int BK  = 16;
    constexpr int SAS = BM + 4;
    constexpr int NA  = (BM * BK) / (4 * 256);
    constexpr int NB  = (BK * BN) / (4 * 256);
    constexpr int TNP = TN / 2;

    __shared__ float sA[2][BK * SAS];
    __shared__ float sB[2][BK * BN];

    const int tid = threadIdx.x;
    const int tx = tid % (BN / TN), ty = tid / (BN / TN);
    const int row0 = blockIdx.y * BM, col0 = blockIdx.x * BN;

    unsigned long long acc[TM][TNP];
    #pragma unroll
    for (int i = 0; i < TM; i++)
        #pragma unroll
        for (int j = 0; j < TNP; j++) acc[i][j] = 0ULL;

    const int nt = (K + BK - 1) / BK;
    float4 pa[NA], pb[NB];

    auto loadA = [&](int k0) {
        #pragma unroll
        for (int i = 0; i < NA; i++) {
            int idx = tid + i * 256;
            int row = idx >> 2, kv = (idx & 3) * 4;
            int gm = row0 + row, gk = k0 + kv;
            float4 v = {0.f, 0.f, 0.f, 0.f};
            if (gm < M && gk < K) v = *reinterpret_cast<const float4*>(A + (size_t)gm * lda + gk);
            pa[i] = v;
        }
    };
    auto loadB = [&](int k0) {
        #pragma unroll
        for (int i = 0; i < NB; i++) {
            int idx = tid + i * 256;
            int kr = idx / (BN / 4), nv = (idx % (BN / 4)) * 4;
            int gk = k0 + kr;
            float4 v = {0.f, 0.f, 0.f, 0.f};
            if (gk < K) v = *reinterpret_cast<const float4*>(B + (size_t)gk * ldb + col0 + nv);
            pb[i] = v;
        }
    };
    auto stage = [&](int buf) {
        #pragma unroll
        for (int i = 0; i < NA; i++) {
            int idx = tid + i * 256;
            int row = idx >> 2, kv = (idx & 3) * 4;
            float* p = &sA[buf][0];
            p[(kv + 0) * SAS + row] = pa[i].x;
            p[(kv + 1) * SAS + row] = pa[i].y;
            p[(kv + 2) * SAS + row] = pa[i].z;
            p[(kv + 3) * SAS + row] = pa[i].w;
        }
        #pragma unroll
        for (int i = 0; i < NB; i++) {
            int idx = tid + i * 256;
            int kr = idx / (BN / 4), nv = (idx % (BN / 4)) * 4;
            *reinterpret_cast<float4*>(&sB[buf][kr * BN + nv]) = pb[i];
        }
    };

    loadA(0); loadB(0);
    stage(0);
    __syncthreads();

    for (int t = 0; t < nt; t++) {
        int buf = t & 1;
        if (t + 1 < nt) { loadA((t + 1) * BK); loadB((t + 1) * BK); }
        #pragma unroll
        for (int kk = 0; kk < BK; kk++) {
            float a[TM];
            #pragma unroll
            for (int i = 0; i < TM; i += 4)
                *reinterpret_cast<float4*>(&a[i]) =
                    *reinterpret_cast<const float4*>(&sA[buf][kk * SAS + ty * TM + i]);
            unsigned long long bp[TNP];
            const unsigned long long* sBp =
                reinterpret_cast<const unsigned long long*>(&sB[buf][kk * BN + tx * TN]);
            #pragma unroll
            for (int j = 0; j < TNP; j++) bp[j] = sBp[j];
            #pragma unroll
            for (int i = 0; i < TM; i++) {
                unsigned long long ap;
                asm("mov.b64 %0, {%1, %1};" : "=l"(ap) : "f"(a[i]));
                #pragma unroll
                for (int j = 0; j < TNP; j++)
                    asm("fma.rn.f32x2 %0, %1, %2, %0;"
                        : "+l"(acc[i][j]) : "l"(ap), "l"(bp[j]));
            }
        }
        if (t + 1 < nt) stage(buf ^ 1);
        __syncthreads();
    }

    #pragma unroll
    for (int i = 0; i < TM; i++) {
        int gm = row0 + ty * TM + i;
        if (gm >= M) continue;
        #pragma unroll
        for (int j = 0; j < TNP; j++) {
            float lo, hi;
            asm("mov.b64 {%0, %1}, %2;" : "=f"(lo), "=f"(hi) : "l"(acc[i][j]));
            int gn = col0 + tx * TN + 2 * j;
            if (bias) { lo += bias[gn]; hi += bias[gn + 1]; }
            if (ACT == 1) { lo = fmaxf(lo, 0.f); hi = fmaxf(hi, 0.f); }
            if (CVT == 1) { lo = tf32r(lo); hi = tf32r(hi); }
            C[(size_t)gm * ldc + gn]     = lo;
            C[(size_t)gm * ldc + gn + 1] = hi;
        }
    }
}

// ---------------- layer-1 CSR aggregate (2-way unrolled edge loop) ----------------
__global__ void agg1_k(const int* __restrict__ adj, const int* __restrict__ ptr,
                       const float* __restrict__ al, const float* __restrict__ hs,
                       const float* __restrict__ b1, const float* __restrict__ fold2,
                       float* __restrict__ out1, float* __restrict__ al2,
                       int dst0, int ndst) {
    __shared__ float  sb[HID];
    __shared__ float2 sf[HID];
    int tid = threadIdx.x, lane = tid & 31;
    for (int i = tid; i < HID; i += blockDim.x) {
        sb[i] = b1[i];
        sf[i] = reinterpret_cast<const float2*>(fold2)[i];
    }
    __syncthreads();
    int rel = (blockIdx.x * blockDim.x + tid) >> 5;
    if (rel >= ndst) return;
    int dst = dst0 + rel;
    int beg = ptr[dst], end = ptr[dst + 1];
    float ald = (lane < 8) ? al[(size_t)dst * 16 + 8 + lane] : 0.f;
    float4 a0 = {0.f, 0.f, 0.f, 0.f}, a1 = {0.f, 0.f, 0.f, 0.f};
    float ss = 0.f;
    int p = beg;
    for (; p + 2 <= end; p += 2) {
        int srcA = adj[p], srcB = adj[p + 1];
        float wA = 0.f, wB = 0.f;
        if (lane < 8) {
            float vA = al[(size_t)srcA * 16 + lane] + ald;
            float vB = al[(size_t)srcB * 16 + lane] + ald;
            vA = (vA > 0.f) ? vA : 0.2f * vA;
            vB = (vB > 0.f) ? vB : 0.2f * vB;
            wA = __expf(vA);
            wB = __expf(vB);
            ss += wA;            // match serial order: edge p then p+1
            ss += wB;
        }
        float wA0 = __shfl_sync(0xffffffffu, wA, lane >> 3);
        float wA1 = __shfl_sync(0xffffffffu, wA, 4 + (lane >> 3));
        float wB0 = __shfl_sync(0xffffffffu, wB, lane >> 3);
        float wB1 = __shfl_sync(0xffffffffu, wB, 4 + (lane >> 3));
        const float4* hvA = reinterpret_cast<const float4*>(hs + (size_t)srcA * HID);
        const float4* hvB = reinterpret_cast<const float4*>(hs + (size_t)srcB * HID);
        float4 hA0 = hvA[lane], hA1 = hvA[32 + lane];
        float4 hB0 = hvB[lane], hB1 = hvB[32 + lane];
        a0.x += wA0 * hA0.x; a0.y += wA0 * hA0.y; a0.z += wA0 * hA0.z; a0.w += wA0 * hA0.w;
        a1.x += wA1 * hA1.x; a1.y += wA1 * hA1.y; a1.z += wA1 * hA1.z; a1.w += wA1 * hA1.w;
        a0.x += wB0 * hB0.x; a0.y += wB0 * hB0.y; a0.z += wB0 * hB0.z; a0.w += wB0 * hB0.w;
        a1.x += wB1 * hB1.x; a1.y += wB1 * hB1.y; a1.z += wB1 * hB1.z; a1.w += wB1 * hB1.w;
    }
    for (; p < end; p++) {
        int src = adj[p];
        float w = 0.f;
        if (lane < 8) {
            float v = al[(size_t)src * 16 + lane] + ald;
            v = (v > 0.f) ? v : 0.2f * v;
            w = __expf(v);
            ss += w;
        }
        float w0 = __shfl_sync(0xffffffffu, w, lane >> 3);
        float w1 = __shfl_sync(0xffffffffu, w, 4 + (lane >> 3));
        const float4* hv = reinterpret_cast<const float4*>(hs + (size_t)src * HID);
        float4 h0 = hv[lane], h1 = hv[32 + lane];
        a0.x += w0 * h0.x; a0.y += w0 * h0.y; a0.z += w0 * h0.z; a0.w += w0 * h0.w;
        a1.x += w1 * h1.x; a1.y += w1 * h1.y; a1.z += w1 * h1.z; a1.w += w1 * h1.w;
    }
    float s0 = __shfl_sync(0xffffffffu, ss, lane >> 3);
    float s1 = __shfl_sync(0xffffffffu, ss, 4 + (lane >> 3));
    float i0 = __fdividef(1.f, s0 + 1e-16f);
    float i1 = __fdividef(1.f, s1 + 1e-16f);
    int c0 = lane * 4, c1 = 128 + lane * 4;
    float4 v0, v1;
    v0.x = a0.x * i0 + sb[c0 + 0];
    v0.y = a0.y * i0 + sb[c0 + 1];
    v0.z = a0.z * i0 + sb[c0 + 2];
    v0.w = a0.w * i0 + sb[c0 + 3];
    v1.x = a1.x * i1 + sb[c1 + 0];
    v1.y = a1.y * i1 + sb[c1 + 1];
    v1.z = a1.z * i1 + sb[c1 + 2];
    v1.w = a1.w * i1 + sb[c1 + 3];
    v0.x = tf32r(v0.x > 0.f ? v0.x : expm1f(v0.x));
    v0.y = tf32r(v0.y > 0.f ? v0.y : expm1f(v0.y));
    v0.z = tf32r(v0.z > 0.f ? v0.z : expm1f(v0.z));
    v0.w = tf32r(v0.w > 0.f ? v0.w : expm1f(v0.w));
    v1.x = tf32r(v1.x > 0.f ? v1.x : expm1f(v1.x));
    v1.y = tf32r(v1.y > 0.f ? v1.y : expm1f(v1.y));
    v1.z = tf32r(v1.z > 0.f ? v1.z : expm1f(v1.z));
    v1.w = tf32r(v1.w > 0.f ? v1.w : expm1f(v1.w));
    float4* ov = reinterpret_cast<float4*>(out1 + (size_t)dst * HID);
    ov[lane] = v0;
    ov[32 + lane] = v1;
    float d0 = v0.x * sf[c0 + 0].x + v0.y * sf[c0 + 1].x + v0.z * sf[c0 + 2].x + v0.w * sf[c0 + 3].x
             + v1.x * sf[c1 + 0].x + v1.y * sf[c1 + 1].x + v1.z * sf[c1 + 2].x + v1.w * sf[c1 + 3].x;
    float d1 = v0.x * sf[c0 + 0].y + v0.y * sf[c0 + 1].y + v0.z * sf[c0 + 2].y + v0.w * sf[c0 + 3].y
             + v1.x * sf[c1 + 0].y + v1.y * sf[c1 + 1].y + v1.z * sf[c1 + 2].y + v1.w * sf[c1 + 3].y;
    #pragma unroll
    for (int o = 16; o > 0; o >>= 1) {
        d0 += __shfl_xor_sync(0xffffffffu, d0, o);
        d1 += __shfl_xor_sync(0xffffffffu, d1, o);
    }
    if (lane == 0) {
        al2[(size_t)dst * 2 + 0] = d0;
        al2[(size_t)dst * 2 + 1] = d1;
    }
}

// ---------------- layer-2 CSR aggregate (2-way unrolled edge loop) ----------------
__global__ void agg2_k(const int* __restrict__ adj, const int* __restrict__ ptr,
                       const float* __restrict__ al2, const float* __restrict__ hs,
                       const float* __restrict__ b2, float* __restrict__ dout,
                       int out_size) {
    __shared__ float sb[HID];
    int tid = threadIdx.x, lane = tid & 31;
    for (int i = tid; i < HID; i += blockDim.x) sb[i] = b2[i];
    __syncthreads();
    int dst = (blockIdx.x * blockDim.x + tid) >> 5;
    if (dst >= NNODES) return;
    int beg = ptr[dst], end = ptr[dst + 1];
    float ald = al2[(size_t)dst * 2 + 1];
    float4 a0 = {0.f, 0.f, 0.f, 0.f}, a1 = {0.f, 0.f, 0.f, 0.f};
    float ss = 0.f;
    int p = beg;
    for (; p + 2 <= end; p += 2) {
        int srcA = adj[p], srcB = adj[p + 1];
        float wA = 0.f, wB = 0.f;
        if (lane == 0) {
            float vA = al2[(size_t)srcA * 2] + ald;
            float vB = al2[(size_t)srcB * 2] + ald;
            vA = (vA > 0.f) ? vA : 0.2f * vA;
            vB = (vB > 0.f) ? vB : 0.2f * vB;
            wA = __expf(vA);
            wB = __expf(vB);
        }
        wA = __shfl_sync(0xffffffffu, wA, 0);
        wB = __shfl_sync(0xffffffffu, wB, 0);
        ss += wA;
        ss += wB;
        const float4* hvA = reinterpret_cast<const float4*>(hs + (size_t)srcA * HID);
        const float4* hvB = reinterpret_cast<const float4*>(hs + (size_t)srcB * HID);
        float4 hA0 = hvA[lane], hA1 = hvA[32 + lane];
        float4 hB0 = hvB[lane], hB1 = hvB[32 + lane];
        a0.x += wA * hA0.x; a0.y += wA * hA0.y; a0.z += wA * hA0.z; a0.w += wA * hA0.w;
        a1.x += wA * hA1.x; a1.y += wA * hA1.y; a1.z += wA * hA1.z; a1.w += wA * hA1.w;
        a0.x += wB * hB0.x; a0.y += wB * hB0.y; a0.z += wB * hB0.z; a0.w += wB * hB0.w;
        a1.x += wB * hB1.x; a1.y += wB * hB1.y; a1.z += wB * hB1.z; a1.w += wB * hB1.w;
    }
    for (; p < end; p++) {
        int src = adj[p];
        float w = 0.f;
        if (lane == 0) {
            float v = al2[(size_t)src * 2] + ald;
            v = (v > 0.f) ? v : 0.2f * v;
            w = __expf(v);
        }
        w = __shfl_sync(0xffffffffu, w, 0);
        ss += w;
        const float4* hv = reinterpret_cast<const float4*>(hs + (size_t)src * HID);
        float4 h0 = hv[lane], h1 = hv[32 + lane];
        a0.x += w * h0.x; a0.y += w * h0.y; a0.z += w * h0.z; a0.w += w * h0.w;
        a1.x += w * h1.x; a1.y += w * h1.y; a1.z += w * h1.z; a1.w += w * h1.w;
    }
    float inv = __fdividef(1.f, ss + 1e-16f);
    int c0 = lane * 4, c1 = 128 + lane * 4;
    float4 v0, v1;
    v0.x = a0.x * inv + sb[c0 + 0];
    v0.y = a0.y * inv + sb[c0 + 1];
    v0.z = a0.z * inv + sb[c0 + 2];
    v0.w = a0.w * inv + sb[c0 + 3];
    v1.x = a1.x * inv + sb[c1 + 0];
    v1.y = a1.y * inv + sb[c1 + 1];
    v1.z = a1.z * inv + sb[c1 + 2];
    v1.w = a1.w * inv + sb[c1 + 3];
    float4* ov = reinterpret_cast<float4*>(dout + (size_t)dst * HID);
    ov[lane] = v0;
    ov[32 + lane] = v1;
    if (dst == 0 && lane == 0) {
        dout[out_size - 3] = 0.0f;
        dout[out_size - 2] = (float)NUSERS;
        dout[out_size - 1] = (float)NNODES;
    }
}

// ---------------- streams (created at static-init time) ----------------
struct StreamPack {
    cudaStream_t s1 = nullptr, s2 = nullptr;
    cudaEvent_t ev0 = nullptr, evPrep = nullptr, evXmov = nullptr;
    cudaEvent_t evCSR = nullptr, evU = nullptr, evL = nullptr;
    bool ok = false;
    StreamPack() {
        ok = (cudaStreamCreateWithFlags(&s1, cudaStreamNonBlocking) == cudaSuccess) &&
             (cudaStreamCreateWithFlags(&s2, cudaStreamNonBlocking) == cudaSuccess) &&
             (cudaEventCreateWithFlags(&ev0,    cudaEventDisableTiming) == cudaSuccess) &&
             (cudaEventCreateWithFlags(&evPrep, cudaEventDisableTiming) == cudaSuccess) &&
             (cudaEventCreateWithFlags(&evXmov, cudaEventDisableTiming) == cudaSuccess) &&
             (cudaEventCreateWithFlags(&evCSR,  cudaEventDisableTiming) == cudaSuccess) &&
             (cudaEventCreateWithFlags(&evU,    cudaEventDisableTiming) == cudaSuccess) &&
             (cudaEventCreateWithFlags(&evL,    cudaEventDisableTiming) == cudaSuccess);
    }
};
static StreamPack g_sp;

// ---------------- launch ----------------
static inline float* symaddr(const void* s) {
    void* p = nullptr;
    cudaGetSymbolAddress(&p, s);
    return (float*)p;
}
static inline int* symaddri(const void* s) {
    void* p = nullptr;
    cudaGetSymbolAddress(&p, s);
    return (int*)p;
}

extern "C" void kernel_launch(void* const* d_in, const int* in_sizes, int n_in,
                              void* d_out, int out_size) {
    const float* mov_x = (const float*)d_in[2];
    const int*   ei    = (const int*)d_in[3];
    const float* uemb  = (const float*)d_in[4];
    const float* iemb  = (const float*)d_in[5];
    const float* gW1 = (const float*)d_in[6];  const float* gb1 = (const float*)d_in[7];
    const float* gW2 = (const float*)d_in[8];  const float* gb2 = (const float*)d_in[9];
    const float* tW1 = (const float*)d_in[10]; const float* tb1 = (const float*)d_in[11];
    const float* tW2 = (const float*)d_in[12]; const float* tb2 = (const float*)d_in[13];
    const float* Ws1 = (const float*)d_in[14]; const float* Wd1 = (const float*)d_in[15];
    const float* as1 = (const float*)d_in[16]; const float* ad1 = (const float*)d_in[17];
    const float* b1  = (const float*)d_in[18];
    const float* Ws2 = (const float*)d_in[19]; const float* Wd2 = (const float*)d_in[20];
    const float* as2 = (const float*)d_in[21]; const float* ad2 = (const float*)d_in[22];
    const float* b2  = (const float*)d_in[23];
    const int E = in_sizes[3] / 2;
    float* out = (float*)d_out;

    float* xmov = symaddr(g_xmov);
    float* th   = symaddr(g_th);
    float* gh   = symaddr(g_gh);
    float* hs1  = symaddr(g_hs1);
    float* out1 = symaddr(g_out1);
    float* hs2  = symaddr(g_hs2);
    float* al1  = symaddr(g_al1);
    float* al2  = symaddr(g_al2);
    float* fold1 = symaddr(g_fold1);
    float* fold2 = symaddr(g_fold2);
    float* bt1  = symaddr(g_bt1);
    float* bt2  = symaddr(g_bt2);
    float* btt  = symaddr(g_btt);
    int* cnt  = symaddri(g_cnt);
    int* cur  = symaddri(g_cur);
    int* ptr  = symaddri(g_ptr);
    int* bsum = symaddri(g_bsum);
    int* adj  = symaddri(g_adj);

    auto nb = [](int n) { return (n + 255) / 256; };

    const int SM128 = 2 * (128 + 128) * 36 * 4;   // 73728
    const int SM64  = 2 * (128 + 64)  * 36 * 4;   // 55296
    cudaFuncSetAttribute(mma_gemm_k<128, 64, 32, 0>, cudaFuncAttributeMaxDynamicSharedMemorySize, SM128);
    cudaFuncSetAttribute(mma_gemm_k<64, 32, 32, 1>,  cudaFuncAttributeMaxDynamicSharedMemorySize, SM64);

    const bool use_streams = g_sp.ok;
    cudaStream_t s0 = 0;
    cudaStream_t s1 = use_streams ? g_sp.s1 : s0;
    cudaStream_t s2 = use_streams ? g_sp.s2 : s0;

    if (use_streams) cudaEventRecord(g_sp.ev0, s0);

    // --- s0: preprocessing ---
    prep_k<<<PGRID, 256, 0, s0>>>(Ws1, Ws2, tW1, iemb, Wd1, as1, ad1, Wd2, as2, ad2,
                                  bt1, bt2, btt, xmov, fold1, fold2);
    if (use_streams) cudaEventRecord(g_sp.evPrep, s0);

    // --- s1: CSR build chain ---
    if (use_streams) cudaStreamWaitEvent(s1, g_sp.ev0, 0);
    zero_cnt_k<<<NBLK, 256, 0, s1>>>(cnt, cur);
    count_k<<<nb(E), 256, 0, s1>>>(ei, E, cnt);
    scan1_k<<<NBLK, 256, 0, s1>>>(cnt, ptr, bsum);
    scan2_k<<<1, 512, 0, s1>>>(bsum, NBLK);
    scan3_k<<<NBLK, 256, 0, s1>>>(ptr, bsum, E);
    fill_adj_k<<<nb(E), 256, 0, s1>>>(ei, E, ptr, cur, adj);
    if (use_streams) cudaEventRecord(g_sp.evCSR, s1);

    // --- s2: user hs1 GEMM ---
    if (use_streams) cudaStreamWaitEvent(s2, g_sp.evPrep, 0);
    mma_gemm_k<128, 64, 32, 0><<<dim3(2, (NUSERS + 127) / 128), 256, SM128, s2>>>(
        uemb, 64, bt1, DMOV, hs1, HID, NUSERS, 64, nullptr);
    if (use_streams) cudaEventRecord(g_sp.evU, s2);

    // --- s0: movie feature pipeline ---
    mma_gemm_k<64, 32, 32, 1><<<dim3(1, (NITEMS + 127) / 128), 256, SM64, s0>>>(
        mov_x + NGEN, MOVLD, btt, NTAGS, th, 64, NITEMS, NTAGS, tb1);
    {
        dim3 g(1, (NITEMS + 127) / 128);
        gemm2_k<128, 64, 8, 4, 1, 0><<<g, 256, 0, s0>>>(mov_x, MOVLD, gW1, 64, gh, 64, NITEMS, 64, NGEN, gb1);
        gemm2_k<128, 64, 8, 4, 0, 1><<<g, 256, 0, s0>>>(gh, 64, gW2, 64, xmov + 64, DMOV, NITEMS, 64, 64, gb2);
        gemm2_k<128, 64, 8, 4, 0, 1><<<g, 256, 0, s0>>>(th, 64, tW2, 64, xmov + 128, DMOV, NITEMS, 64, 64, tb2);
    }
    if (use_streams) cudaEventRecord(g_sp.evXmov, s0);

    // --- s2: layer-1 logits ---
    if (use_streams) cudaStreamWaitEvent(s2, g_sp.evXmov, 0);
    logits_all_k<<<nb(NNODES * 32), 256, 0, s2>>>(uemb, xmov, fold1, al1);
    if (use_streams) cudaEventRecord(g_sp.evL, s2);

    // --- s0: movie hs1 GEMM ---
    mma_gemm_k<128, 64, 32, 0><<<dim3(2, (NITEMS + 127) / 128), 256, SM128, s0>>>(
        xmov, DMOV, bt1, DMOV, hs1 + (size_t)NUSERS * HID, HID, NITEMS, DMOV, nullptr);

    // --- join: agg1 needs CSR, hs1 (user+movie), al1 ---
    if (use_streams) {
        cudaStreamWaitEvent(s0, g_sp.evCSR, 0);
        cudaStreamWaitEvent(s0, g_sp.evU, 0);
        cudaStreamWaitEvent(s0, g_sp.evL, 0);
    }
    agg1_k<<<nb(NNODES * 32), 256, 0, s0>>>(adj, ptr, al1, hs1, b1, fold2, out1, al2,
                                            0, NNODES);

    // ---- GAT layer 2 (serial tail) ----
    mma_gemm_k<128, 64, 32, 0><<<dim3(2, (NNODES + 127) / 128), 256, SM128, s0>>>(
        out1, HID, bt2, HID, hs2, HID, NNODES, HID, nullptr);

    agg2_k<<<nb(NNODES * 32), 256, 0, s0>>>(adj, ptr, al2, hs2, b2, out, out_size);
}